// round 12
// baseline (speedup 1.0000x reference)
#include <cuda_runtime.h>
#include <cuda_fp16.h>
#include <math.h>
#include <stdint.h>

#define NT 8192
#define CD 1024
#define HD 4096
#define RC_CAP 512

// ---------------- scratch ----------------------------------------------------
__device__ __align__(16) float g_xln[NT * CD];
__device__ __align__(16) float g_r[NT * CD];
__device__ __align__(16) float g_a[NT * CD];
__device__ float g_scale[NT];
__device__ int g_cnt[3];
__device__ int g_list[3 * NT];
__device__ int g_winner[NT];
__device__ float g_conf3[3 * NT];
__device__ int g_rc_cnt;
__device__ int g_rc_list[RC_CAP];
__device__ __align__(16) __half g_xh[NT * CD];
__device__ __align__(16) __half g_hh[NT * CD];
__device__ __align__(16) __half g_sh[NT * CD];
__device__ __align__(16) __half g_ah[NT * CD];
__device__ __align__(16) __half g_hr0[NT * HD];
__device__ __align__(16) __half g_hr1[NT * HD];
#define WSZ (23u * 1048576u)
__device__ __align__(16) __half g_wt[WSZ];

// ---------------- helpers ----------------------------------------------------
__device__ __forceinline__ uint32_t smem_u32(const void* p) {
    uint32_t a;
    asm("{ .reg .u64 t; cvta.to.shared.u64 t, %1; cvt.u32.u64 %0, t; }" : "=r"(a) : "l"(p));
    return a;
}
__device__ __forceinline__ void ldsm4(uint32_t* r, uint32_t a) {
    asm volatile("ldmatrix.sync.aligned.m8n8.x4.shared.b16 {%0,%1,%2,%3}, [%4];"
                 : "=r"(r[0]), "=r"(r[1]), "=r"(r[2]), "=r"(r[3]) : "r"(a));
}
__device__ __forceinline__ void mma16816(float* d, const uint32_t* a, const uint32_t* b) {
    asm volatile("mma.sync.aligned.m16n8k16.row.col.f32.f16.f16.f32 "
                 "{%0,%1,%2,%3}, {%4,%5,%6,%7}, {%8,%9}, {%0,%1,%2,%3};"
                 : "+f"(d[0]), "+f"(d[1]), "+f"(d[2]), "+f"(d[3])
                 : "r"(a[0]), "r"(a[1]), "r"(a[2]), "r"(a[3]), "r"(b[0]), "r"(b[1]));
}
__device__ __forceinline__ void cpa16(uint32_t s, const void* g) {
    asm volatile("cp.async.ca.shared.global [%0], [%1], 16;" :: "r"(s), "l"(g));
}
__device__ __forceinline__ float sigf(float x) { return 1.0f / (1.0f + expf(-x)); }
__device__ __forceinline__ unsigned packh(__half a, __half b) {
    return (unsigned)__half_as_ushort(a) | ((unsigned)__half_as_ushort(b) << 16);
}

// ================= HMMA tensor GEMM core (single fp16) ========================
enum { TEPI_HR = 0, TEPI_STORE = 1, TEPI_GATE = 2, TEPI_SCATTER = 3,
       TEPI_CVT = 4, TEPI_GATE2 = 5, TEPI_ADDX = 6 };
// per buffer: A 16KB @0, B 16KB @16384; 3 buffers (single-sync ring)
#define TG_SMEM (3 * 32768 + 1024)

struct GDesc {
    const __half *Ah, *Bh;
    const int* Mptr;
    const int* gidx;
    const float* aux;
    const int* sidx;
    const float* scl;
    float* outF;
    __half* outH;
    int K, ldo, Nb;
};

__device__ __forceinline__ void tg_main(
    const __half* __restrict__ Ah, const __half* __restrict__ Bh,
    int M, int bm, int bn, int K, const int* __restrict__ gidx,
    uint32_t smb, float acc[4][4][4]) {
    int tid = threadIdx.x, lane = tid & 31, warp = tid >> 5;
    int wm = warp & 1, wn = warp >> 1;
    int quad = lane >> 3, r8 = lane & 7;

    uint32_t baseA[4], maskA[4];
    uint32_t kqA = (uint32_t)(quad >> 1) * 16;
#pragma unroll
    for (int mt = 0; mt < 4; mt++) {
        int rowA = wm * 64 + mt * 16 + (quad & 1) * 8 + r8;
        baseA[mt] = (uint32_t)rowA * 128;
        maskA[mt] = (uint32_t)(rowA & 7) << 4;
    }
    uint32_t baseB[2], maskB[2];
    uint32_t kqB = (uint32_t)(quad & 1) * 16;
#pragma unroll
    for (int n2 = 0; n2 < 2; n2++) {
        int rowB = wn * 32 + n2 * 16 + (quad >> 1) * 8 + r8;
        baseB[n2] = 16384u + (uint32_t)rowB * 128;
        maskB[n2] = (uint32_t)(rowB & 7) << 4;
    }

    int row = tid >> 1, h = tid & 1;
    int ra = bm + row; if (ra > M - 1) ra = M - 1;
    if (gidx) ra = gidx[ra];
    const __half* pA = Ah + (size_t)ra * K + h * 32;
    const __half* pB = Bh + (size_t)(bn + row) * K + h * 32;
    uint32_t mk = (uint32_t)(row & 7) << 4;
    uint32_t st[4];
#pragma unroll
    for (int i = 0; i < 4; i++)
        st[i] = (uint32_t)row * 128 + (((uint32_t)h * 64 + i * 16) ^ mk);

    auto stage = [&](int t, int buf) {
        int kc = t * 64;
        uint32_t ab = smb + (uint32_t)buf * 32768u;
#pragma unroll
        for (int i = 0; i < 4; i++) {
            cpa16(ab + st[i],          pA + kc + i * 8);
            cpa16(ab + 16384u + st[i], pB + kc + i * 8);
        }
        asm volatile("cp.async.commit_group;" ::: "memory");
    };

#pragma unroll
    for (int i = 0; i < 4; i++)
#pragma unroll
        for (int j = 0; j < 4; j++)
#pragma unroll
            for (int q = 0; q < 4; q++) acc[i][j][q] = 0.f;

    int nch = K >> 6;
    stage(0, 0);
    stage(1, 1);
    int b0 = 0;
    for (int t = 0; t < nch; t++) {
        if (t + 1 < nch) asm volatile("cp.async.wait_group 1;" ::: "memory");
        else             asm volatile("cp.async.wait_group 0;" ::: "memory");
        __syncthreads();
        if (t + 2 < nch) {
            int nb = b0 + 2; if (nb >= 3) nb -= 3;
            stage(t + 2, nb);
        }
        uint32_t bufs = smb + (uint32_t)b0 * 32768u;
#pragma unroll
        for (int ks = 0; ks < 4; ks++) {
            uint32_t cb = (uint32_t)ks * 32;
            uint32_t bfr[4][2];
#pragma unroll
            for (int n2 = 0; n2 < 2; n2++) {
                uint32_t r[4];
                ldsm4(r, bufs + baseB[n2] + ((kqB + cb) ^ maskB[n2]));
                bfr[2 * n2][0] = r[0]; bfr[2 * n2][1] = r[1];
                bfr[2 * n2 + 1][0] = r[2]; bfr[2 * n2 + 1][1] = r[3];
            }
#pragma unroll
            for (int mt = 0; mt < 4; mt++) {
                uint32_t a[4];
                ldsm4(a, bufs + baseA[mt] + ((kqA + cb) ^ maskA[mt]));
#pragma unroll
                for (int nt = 0; nt < 4; nt++)
                    mma16816(acc[mt][nt], a, bfr[nt]);
            }
        }
        b0++; if (b0 == 3) b0 = 0;
    }
}

template <int EPI>
__device__ __forceinline__ void emit2(int grow, int gcol, float v0, float v1, int M,
                                      const float* __restrict__ aux,
                                      const int* __restrict__ sidx, const float* __restrict__ scl,
                                      float* __restrict__ outF, __half* __restrict__ outH, int ldo) {
    if (grow >= M) return;
    if (EPI == TEPI_STORE) {
        *(float2*)(outF + (size_t)grow * ldo + gcol) = make_float2(v0, v1);
    } else if (EPI == TEPI_ADDX) {
        float2 a = *(const float2*)(aux + (size_t)grow * CD + gcol);
        *(float2*)(outF + (size_t)grow * ldo + gcol) = make_float2(v0 + a.x, v1 + a.y);
    } else if (EPI == TEPI_SCATTER) {
        int orow = sidx[grow];
        float sc = scl[orow];
        float2* p = (float2*)(outF + (size_t)orow * ldo + gcol);
        float2 c = *p;
        c.x += v0 * sc; c.y += v1 * sc;
        *p = c;
    } else {
        if (EPI == TEPI_HR) {
            v0 = fmaxf(v0, 0.f); v0 *= v0;
            v1 = fmaxf(v1, 0.f); v1 *= v1;
        } else if (EPI == TEPI_GATE) {
            float2 a = *(const float2*)(aux + (size_t)grow * CD + gcol);
            v0 = a.x * sigf(v0); v1 = a.y * sigf(v1);
        } else if (EPI == TEPI_GATE2) {
            float2 a = *(const float2*)(aux + (size_t)grow * CD + gcol);
            v0 = sigf(a.x) * v0; v1 = sigf(a.y) * v1;
        }
        *(unsigned*)(outH + (size_t)grow * ldo + gcol) =
            packh(__float2half_rn(v0), __float2half_rn(v1));
    }
}

template <int EPI>
__device__ __forceinline__ void tg_epi(int M, int bm, int bn, float acc[4][4][4],
                                       const float* aux, const int* sidx, const float* scl,
                                       float* outF, __half* outH, int ldo) {
    int lane = threadIdx.x & 31, warp = threadIdx.x >> 5;
    int wm = warp & 1, wn = warp >> 1;
    int erow = lane >> 2, ecol = (lane & 3) * 2;
#pragma unroll
    for (int mt = 0; mt < 4; mt++) {
        int gr = bm + wm * 64 + mt * 16 + erow;
#pragma unroll
        for (int nt = 0; nt < 4; nt++) {
            int gc = bn + wn * 32 + nt * 8 + ecol;
            emit2<EPI>(gr,     gc, acc[mt][nt][0], acc[mt][nt][1], M, aux, sidx, scl, outF, outH, ldo);
            emit2<EPI>(gr + 8, gc, acc[mt][nt][2], acc[mt][nt][3], M, aux, sidx, scl, outF, outH, ldo);
        }
    }
}

template <int EPI>
__global__ void __launch_bounds__(256, 2)
tgemm(const __half* __restrict__ Ah, const __half* __restrict__ Bh,
      int Mstat, const int* __restrict__ Mptr, int K,
      const int* __restrict__ gidx, const float* __restrict__ aux,
      const int* __restrict__ sidx, const float* __restrict__ scl,
      float* __restrict__ outF, __half* __restrict__ outH, int ldo) {
    int M = Mptr ? *Mptr : Mstat;
    int bm = blockIdx.x * 128;
    if (bm >= M) return;
    int bn = blockIdx.y * 128;
    extern __shared__ char smraw[];
    uint32_t smb0 = smem_u32(smraw);
    uint32_t smb = (smb0 + 1023u) & ~1023u;
    float acc[4][4][4];
    tg_main(Ah, Bh, M, bm, bn, K, gidx, smb, acc);
    tg_epi<EPI>(M, bm, bn, acc, aux, sidx, scl, outF, outH, ldo);
}

template <int E0, int E1, int E2, int E3>
__global__ void __launch_bounds__(256, 2)
btgemm(GDesc g0, GDesc g1, GDesc g2, GDesc g3) {
    int z = blockIdx.z;
    GDesc g = (z == 0) ? g0 : (z == 1) ? g1 : (z == 2) ? g2 : g3;
    if ((int)blockIdx.y >= g.Nb) return;
    int M = *g.Mptr;
    int bm = blockIdx.x * 128;
    if (bm >= M) return;
    int bn = blockIdx.y * 128;
    extern __shared__ char smraw[];
    uint32_t smb0 = smem_u32(smraw);
    uint32_t smb = (smb0 + 1023u) & ~1023u;
    float acc[4][4][4];
    tg_main(g.Ah, g.Bh, M, bm, bn, g.K, g.gidx, smb, acc);
    if (z == 0)      tg_epi<E0>(M, bm, bn, acc, g.aux, g.sidx, g.scl, g.outF, g.outH, g.ldo);
    else if (z == 1) tg_epi<E1>(M, bm, bn, acc, g.aux, g.sidx, g.scl, g.outF, g.outH, g.ldo);
    else if (z == 2) tg_epi<E2>(M, bm, bn, acc, g.aux, g.sidx, g.scl, g.outF, g.outH, g.ldo);
    else             tg_epi<E3>(M, bm, bn, acc, g.aux, g.sidx, g.scl, g.outF, g.outH, g.ldo);
}

// ======== batched transpose + convert: W[K,N] -> WT[N,K] (fp16) ===============
struct TSArgs {
    const float* W[8];
    __half* O[8];
    int K, N;
};
__global__ void tsplit_b(TSArgs a) {
    __shared__ float t[32][33];
    const float* W = a.W[blockIdx.z];
    __half* O = a.O[blockIdx.z];
    int K = a.K, N = a.N;
    int n0 = blockIdx.x * 32, k0 = blockIdx.y * 32;
    int tx = threadIdx.x, ty = threadIdx.y;
#pragma unroll
    for (int j = 0; j < 4; j++)
        t[ty + 8 * j][tx] = W[(size_t)(k0 + ty + 8 * j) * N + n0 + tx];
    __syncthreads();
#pragma unroll
    for (int j = 0; j < 4; j++) {
        float v = t[tx][ty + 8 * j];
        O[(size_t)(n0 + ty + 8 * j) * K + k0 + tx] = __float2half_rn(v);
    }
}

// ================= LN / routing ===============================================
__device__ __forceinline__ float blockReduceSum(float v) {
    __shared__ float sh[8];
#pragma unroll
    for (int o = 16; o > 0; o >>= 1) v += __shfl_down_sync(0xffffffffu, v, o);
    int w = threadIdx.x >> 5, l = threadIdx.x & 31;
    if (l == 0) sh[w] = v;
    __syncthreads();
    if (threadIdx.x < 8) {
        float r = sh[threadIdx.x];
#pragma unroll
        for (int o = 4; o > 0; o >>= 1) r += __shfl_down_sync(0x000000ffu, r, o);
        if (threadIdx.x == 0) sh[0] = r;
    }
    __syncthreads();
    float res = sh[0];
    __syncthreads();
    return res;
}

__global__ void ln_kernel(const float* __restrict__ x, const float* __restrict__ w,
                          const float* __restrict__ b, float* __restrict__ out,
                          __half* __restrict__ oh) {
    int row = blockIdx.x, tid = threadIdx.x;
    float4 v = ((const float4*)(x + (size_t)row * CD))[tid];
    float s = blockReduceSum(v.x + v.y + v.z + v.w);
    float mean = s * (1.0f / CD);
    float dx = v.x - mean, dy = v.y - mean, dz = v.z - mean, dw = v.w - mean;
    float s2 = blockReduceSum(dx * dx + dy * dy + dz * dz + dw * dw);
    float rstd = 1.0f / sqrtf(s2 * (1.0f / CD) + 1e-5f);
    float4 wv = ((const float4*)w)[tid], bv = ((const float4*)b)[tid];
    float4 o = make_float4(dx * rstd * wv.x + bv.x, dy * rstd * wv.y + bv.y,
                           dz * rstd * wv.z + bv.z, dw * rstd * wv.w + bv.w);
    ((float4*)(out + (size_t)row * CD))[tid] = o;
    ((uint2*)(oh + (size_t)row * CD))[tid] =
        make_uint2(packh(__float2half_rn(o.x), __float2half_rn(o.y)),
                   packh(__float2half_rn(o.z), __float2half_rn(o.w)));
}

__global__ void ln2_route_kernel(const float* __restrict__ x2, const float* __restrict__ w,
                                 const float* __restrict__ b, const float* __restrict__ conf_rwkv,
                                 const float* __restrict__ conf_trans, const float* __restrict__ w_diff,
                                 const float* __restrict__ W_aff, const float* __restrict__ capital,
                                 __half* __restrict__ hh,
                                 float* __restrict__ conf3, int* __restrict__ winner,
                                 int* __restrict__ rc_cnt, int* __restrict__ rc_list) {
    int row = blockIdx.x, tid = threadIdx.x;
    float4 v = ((const float4*)(x2 + (size_t)row * CD))[tid];
    float s = blockReduceSum(v.x + v.y + v.z + v.w);
    float mean = s * (1.0f / CD);
    float dx = v.x - mean, dy = v.y - mean, dz = v.z - mean, dw = v.w - mean;
    float s2 = blockReduceSum(dx * dx + dy * dy + dz * dz + dw * dw);
    float rstd = 1.0f / sqrtf(s2 * (1.0f / CD) + 1e-5f);
    float4 wv = ((const float4*)w)[tid], bv = ((const float4*)b)[tid];
    float4 o = make_float4(dx * rstd * wv.x + bv.x, dy * rstd * wv.y + bv.y,
                           dz * rstd * wv.z + bv.z, dw * rstd * wv.w + bv.w);
    ((uint2*)(hh + (size_t)row * CD))[tid] =
        make_uint2(packh(__float2half_rn(o.x), __float2half_rn(o.y)),
                   packh(__float2half_rn(o.z), __float2half_rn(o.w)));

    float p[7];
    float4 c0 = ((const float4*)conf_rwkv)[tid];
    float4 c1 = ((const float4*)(conf_rwkv + CD))[tid];
    float4 ct = ((const float4*)conf_trans)[tid];
    float4 wd = ((const float4*)w_diff)[tid];
    p[0] = o.x * c0.x + o.y * c0.y + o.z * c0.z + o.w * c0.w;
    p[1] = o.x * c1.x + o.y * c1.y + o.z * c1.z + o.w * c1.w;
    p[2] = o.x * ct.x + o.y * ct.y + o.z * ct.z + o.w * ct.w;
    p[3] = o.x * wd.x + o.y * wd.y + o.z * wd.z + o.w * wd.w;
    const float* wa = W_aff + (size_t)tid * 12;
#pragma unroll
    for (int e = 0; e < 3; e++)
        p[4 + e] = o.x * wa[e] + o.y * wa[3 + e] + o.z * wa[6 + e] + o.w * wa[9 + e];

    __shared__ float red[7][8];
    int wid = tid >> 5, lid = tid & 31;
#pragma unroll
    for (int q = 0; q < 7; q++) {
        float vv = p[q];
#pragma unroll
        for (int o2 = 16; o2 > 0; o2 >>= 1) vv += __shfl_down_sync(0xffffffffu, vv, o2);
        if (lid == 0) red[q][wid] = vv;
    }
    __syncthreads();
    if (tid == 0) {
        float d[7];
#pragma unroll
        for (int q = 0; q < 7; q++) {
            float t = 0.f;
#pragma unroll
            for (int k = 0; k < 8; k++) t += red[q][k];
            d[q] = t;
        }
        float cf[3] = {sigf(d[0]), sigf(d[1]), sigf(d[2])};
        float diff = sigf(d[3]);
        float bids[3];
#pragma unroll
        for (int e = 0; e < 3; e++) {
            bids[e] = cf[e] * capital[e] * diff + d[4 + e];
            conf3[row * 3 + e] = cf[e];
        }
        int wdx = 0; float best = bids[0];
        if (bids[1] > best) { best = bids[1]; wdx = 1; }
        if (bids[2] > best) { best = bids[2]; wdx = 2; }
        float second = -1e30f;
#pragma unroll
        for (int e = 0; e < 3; e++)
            if (e != wdx && bids[e] > second) second = bids[e];
        winner[row] = wdx;
        if (best - second < 1e-3f) {
            int pos = atomicAdd(rc_cnt, 1);
            if (pos < RC_CAP) rc_list[pos] = row;
        }
    }
}

// exact fp32 recompute of routing for marginal tokens (coalesced row-major GEMV)
__global__ void recheck_kernel(const float* __restrict__ x, const float* __restrict__ xln,
                               const float* __restrict__ Wr, const float* __restrict__ Wv,
                               const float* __restrict__ Wo,
                               const float* __restrict__ ln2w, const float* __restrict__ ln2b,
                               const float* __restrict__ conf_rwkv, const float* __restrict__ conf_trans,
                               const float* __restrict__ w_diff, const float* __restrict__ W_aff,
                               const float* __restrict__ capital,
                               const int* __restrict__ rc_cnt, const int* __restrict__ rc_list,
                               int* __restrict__ winner) {
    int n = *rc_cnt; if (n > RC_CAP) n = RC_CAP;
    int bi = blockIdx.x;
    if (bi >= n) return;
    int row = rc_list[bi];
    int tid = threadIdx.x;
    __shared__ float sx[CD];
    __shared__ float su[CD];
    for (int c = tid; c < CD; c += 256) sx[c] = xln[(size_t)row * CD + c];
    __syncthreads();

    float racc[4] = {0, 0, 0, 0}, vacc[4] = {0, 0, 0, 0};
    for (int k = 0; k < CD; k++) {
        float xv = sx[k];
        const float* wr = Wr + (size_t)k * CD + tid;
        const float* wv = Wv + (size_t)k * CD + tid;
#pragma unroll
        for (int j = 0; j < 4; j++) {
            racc[j] += xv * wr[j * 256];
            vacc[j] += xv * wv[j * 256];
        }
    }
#pragma unroll
    for (int j = 0; j < 4; j++)
        su[tid + j * 256] = sigf(racc[j]) * vacc[j];
    __syncthreads();

    float oacc[4] = {0, 0, 0, 0};
    for (int k = 0; k < CD; k++) {
        float uv = su[k];
        const float* wo = Wo + (size_t)k * CD + tid;
#pragma unroll
        for (int j = 0; j < 4; j++) oacc[j] += uv * wo[j * 256];
    }
    __syncthreads();
#pragma unroll
    for (int j = 0; j < 4; j++)
        sx[tid + j * 256] = oacc[j] + x[(size_t)row * CD + tid + j * 256];
    __syncthreads();

    float ps = 0.f;
    for (int c = tid; c < CD; c += 256) ps += sx[c];
    float mean = blockReduceSum(ps) * (1.0f / CD);
    float ps2 = 0.f;
    for (int c = tid; c < CD; c += 256) { float d = sx[c] - mean; ps2 += d * d; }
    float rstd = 1.0f / sqrtf(blockReduceSum(ps2) * (1.0f / CD) + 1e-5f);

    float p[7] = {0, 0, 0, 0, 0, 0, 0};
    for (int c = tid; c < CD; c += 256) {
        float hc = (sx[c] - mean) * rstd * ln2w[c] + ln2b[c];
        p[0] += hc * conf_rwkv[c];
        p[1] += hc * conf_rwkv[CD + c];
        p[2] += hc * conf_trans[c];
        p[3] += hc * w_diff[c];
        p[4] += hc * W_aff[c * 3 + 0];
        p[5] += hc * W_aff[c * 3 + 1];
        p[6] += hc * W_aff[c * 3 + 2];
    }
    __shared__ float red[7][8];
    int wid = tid >> 5, lid = tid & 31;
#pragma unroll
    for (int q = 0; q < 7; q++) {
        float vv = p[q];
#pragma unroll
        for (int o2 = 16; o2 > 0; o2 >>= 1) vv += __shfl_down_sync(0xffffffffu, vv, o2);
        if (lid == 0) red[q][wid] = vv;
    }
    __syncthreads();
    if (tid == 0) {
        float d[7];
#pragma unroll
        for (int q = 0; q < 7; q++) {
            float t = 0.f;
#pragma unroll
            for (int k = 0; k < 8; k++) t += red[q][k];
            d[q] = t;
        }
        float cf[3] = {sigf(d[0]), sigf(d[1]), sigf(d[2])};
        float diff = sigf(d[3]);
        int wdx = 0; float best = -1e30f;
#pragma unroll
        for (int e = 0; e < 3; e++) {
            float bid = cf[e] * capital[e] * diff + d[4 + e];
            if (bid > best) { best = bid; wdx = e; }
        }
        winner[row] = wdx;
    }
}

__global__ void build_lists(const int* __restrict__ winner, const float* __restrict__ conf3,
                            float* __restrict__ scale_out, int* __restrict__ cnt, int* __restrict__ lst) {
    int i = blockIdx.x * 256 + threadIdx.x;
    if (i >= NT) return;
    int w = winner[i];
    float wc = conf3[i * 3 + w];
    scale_out[i] = wc / (wc + 1e-6f);
    int pos = atomicAdd(&cnt[w], 1);
    lst[w * NT + pos] = i;
}

__global__ void zero_cnt_kernel(int* c, int* rc) {
    if (threadIdx.x < 3) c[threadIdx.x] = 0;
    if (threadIdx.x == 0) *rc = 0;
}

// ================= launch =====================================================
extern "C" void kernel_launch(void* const* d_in, const int* in_sizes, int n_in,
                              void* d_out, int out_size) {
    const float* x = (const float*)d_in[0];
    const float* capital = (const float*)d_in[2];
    const float* ln1w = (const float*)d_in[3], *ln1b = (const float*)d_in[4];
    const float* ln2w = (const float*)d_in[5], *ln2b = (const float*)d_in[6];
    const float* Wr = (const float*)d_in[7], *Wv = (const float*)d_in[8];
    const float* Wo = (const float*)d_in[9], *Ws = (const float*)d_in[10];
    const float* Kr = (const float*)d_in[11], *Vr = (const float*)d_in[12];
    const float* confr = (const float*)d_in[13];
    const float* W1 = (const float*)d_in[14], *W2 = (const float*)d_in[15];
    const float* W3 = (const float*)d_in[16];
    const float* conft = (const float*)d_in[17], *wdiff = (const float*)d_in[18];
    const float* Waff = (const float*)d_in[19];
    float* out = (float*)d_out;

    void* p;
    cudaGetSymbolAddress(&p, g_xln);    float* xln = (float*)p;
    cudaGetSymbolAddress(&p, g_r);      float* rb = (float*)p;
    cudaGetSymbolAddress(&p, g_a);      float* ab = (float*)p;
    cudaGetSymbolAddress(&p, g_scale);  float* sclp = (float*)p;
    cudaGetSymbolAddress(&p, g_cnt);    int* cnt = (int*)p;
    cudaGetSymbolAddress(&p, g_list);   int* lst = (int*)p;
    cudaGetSymbolAddress(&p, g_winner); int* win = (int*)p;
    cudaGetSymbolAddress(&p, g_conf3);  float* conf3 = (float*)p;
    cudaGetSymbolAddress(&p, g_rc_cnt); int* rc_cnt = (int*)p;
    cudaGetSymbolAddress(&p, g_rc_list);int* rc_list = (int*)p;
    cudaGetSymbolAddress(&p, g_xh);     __half* xh = (__half*)p;
    cudaGetSymbolAddress(&p, g_hh);     __half* hh = (__half*)p;
    cudaGetSymbolAddress(&p, g_sh);     __half* sh = (__half*)p;
    cudaGetSymbolAddress(&p, g_ah);     __half* ah = (__half*)p;
    cudaGetSymbolAddress(&p, g_hr0);    __half* hr0 = (__half*)p;
    cudaGetSymbolAddress(&p, g_hr1);    __half* hr1 = (__half*)p;
    cudaGetSymbolAddress(&p, g_wt);     __half* wt = (__half*)p;

    cudaFuncSetAttribute(tgemm<TEPI_STORE>,   cudaFuncAttributeMaxDynamicSharedMemorySize, TG_SMEM);
    cudaFuncSetAttribute(tgemm<TEPI_GATE2>,   cudaFuncAttributeMaxDynamicSharedMemorySize, TG_SMEM);
    cudaFuncSetAttribute(tgemm<TEPI_ADDX>,    cudaFuncAttributeMaxDynamicSharedMemorySize, TG_SMEM);
    cudaFuncSetAttribute(tgemm<TEPI_SCATTER>, cudaFuncAttributeMaxDynamicSharedMemorySize, TG_SMEM);
    cudaFuncSetAttribute((const void*)btgemm<TEPI_CVT, TEPI_STORE, TEPI_HR, TEPI_HR>,
                         cudaFuncAttributeMaxDynamicSharedMemorySize, TG_SMEM);
    cudaFuncSetAttribute((const void*)btgemm<TEPI_GATE, TEPI_SCATTER, TEPI_SCATTER, TEPI_SCATTER>,
                         cudaFuncAttributeMaxDynamicSharedMemorySize, TG_SMEM);

    const size_t M1 = 1048576;
    const size_t KR0T = 0, KR1T = 4 * M1, VR0T = 8 * M1, VR1T = 12 * M1;
    const size_t W1T = 16 * M1, W2T = 17 * M1, W3T = 18 * M1;
    const size_t WRT = 19 * M1, WVT = 20 * M1, WOT = 21 * M1, WST = 22 * M1;

    dim3 blk(256), tb(32, 8);
    dim3 gC(NT / 128, CD / 128);

    // weight transpose+convert (fp16), batched: 3 launches
    {
        TSArgs a{};
        a.W[0] = W1; a.O[0] = wt + W1T;
        a.W[1] = W2; a.O[1] = wt + W2T;
        a.W[2] = W3; a.O[2] = wt + W3T;
        a.W[3] = Wr; a.O[3] = wt + WRT;
        a.W[4] = Wv; a.O[4] = wt + WVT;
        a.W[5] = Wo; a.O[5] = wt + WOT;
        a.W[6] = Ws; a.O[6] = wt + WST;
        a.K = CD; a.N = CD;
        tsplit_b<<<dim3(CD / 32, CD / 32, 7), tb>>>(a);
    }
    {
        TSArgs a{};
        a.W[0] = Kr;                     a.O[0] = wt + KR0T;
        a.W[1] = Kr + (size_t)CD * HD;   a.O[1] = wt + KR1T;
        a.K = CD; a.N = HD;
        tsplit_b<<<dim3(HD / 32, CD / 32, 2), tb>>>(a);
    }
    {
        TSArgs a{};
        a.W[0] = Vr;                     a.O[0] = wt + VR0T;
        a.W[1] = Vr + (size_t)HD * CD;   a.O[1] = wt + VR1T;
        a.K = HD; a.N = CD;
        tsplit_b<<<dim3(CD / 32, HD / 32, 2), tb>>>(a);
    }

    zero_cnt_kernel<<<1, 32>>>(cnt, rc_cnt);
    ln_kernel<<<NT, 256>>>(x, ln1w, ln1b, xln, xh);

    // attention path: single-fp16 HMMA
    tgemm<TEPI_STORE><<<gC, blk, TG_SMEM>>>(xh, wt + WRT, NT, nullptr, CD,
                                            nullptr, nullptr, nullptr, nullptr, rb, nullptr, CD);
    tgemm<TEPI_GATE2><<<gC, blk, TG_SMEM>>>(xh, wt + WVT, NT, nullptr, CD,
                                            nullptr, rb, nullptr, nullptr, nullptr, ah, CD);
    tgemm<TEPI_ADDX><<<gC, blk, TG_SMEM>>>(ah, wt + WOT, NT, nullptr, CD,
                                           nullptr, x, nullptr, nullptr, out, nullptr, CD);

    // routing (provisional, flags marginal tokens) -> exact recheck -> lists
    ln2_route_kernel<<<NT, 256>>>(out, ln2w, ln2b, confr, conft, wdiff, Waff, capital,
                                  hh, conf3, win, rc_cnt, rc_list);
    recheck_kernel<<<RC_CAP, 256>>>(x, xln, Wr, Wv, Wo, ln2w, ln2b, confr, conft, wdiff,
                                    Waff, capital, rc_cnt, rc_list, win);
    build_lists<<<NT / 256, 256>>>(win, conf3, sclp, cnt, lst);

    // ---- batched expert set 1: {Ws(sparse,cvt), W1, K0, K1} ----
    GDesc dws = {xh, wt + WST, cnt + 2, lst + 2 * NT,
                 nullptr, nullptr, nullptr, nullptr, sh, CD, CD, 8};
    GDesc dw1 = {hh, wt + W1T, cnt + 2, lst + 2 * NT,
                 nullptr, nullptr, nullptr, ab, nullptr, CD, CD, 8};
    GDesc dk0 = {hh, wt + KR0T, cnt + 0, lst + 0 * NT,
                 nullptr, nullptr, nullptr, nullptr, hr0, CD, HD, 32};
    GDesc dk1 = {hh, wt + KR1T, cnt + 1, lst + 1 * NT,
                 nullptr, nullptr, nullptr, nullptr, hr1, CD, HD, 32};
    btgemm<TEPI_CVT, TEPI_STORE, TEPI_HR, TEPI_HR>
        <<<dim3(NT / 128, 32, 4), blk, TG_SMEM>>>(dws, dw1, dk0, dk1);

    // ---- batched expert set 2: {W2(gate), V0, V1} ----
    GDesc dw2 = {sh, wt + W2T, cnt + 2, nullptr,
                 ab, nullptr, nullptr, nullptr, ah, CD, CD, 8};
    GDesc dv0 = {hr0, wt + VR0T, cnt + 0, nullptr,
                 nullptr, lst + 0 * NT, sclp, out, nullptr, HD, CD, 8};
    GDesc dv1 = {hr1, wt + VR1T, cnt + 1, nullptr,
                 nullptr, lst + 1 * NT, sclp, out, nullptr, HD, CD, 8};
    btgemm<TEPI_GATE, TEPI_SCATTER, TEPI_SCATTER, TEPI_SCATTER>
        <<<dim3(NT / 128, 8, 3), blk, TG_SMEM>>>(dw2, dv0, dv1, dv1);

    // ---- set 3: W3 (scatter) ----
    tgemm<TEPI_SCATTER><<<gC, blk, TG_SMEM>>>(ah, wt + W3T, 0, cnt + 2, CD,
                                              nullptr, nullptr, lst + 2 * NT, sclp, out, nullptr, CD);
}

// round 13
// speedup vs baseline: 1.0706x; 1.0706x over previous
#include <cuda_runtime.h>
#include <cuda_fp16.h>
#include <math.h>
#include <stdint.h>

#define NT 8192
#define CD 1024
#define HD 4096
#define RC_CAP 512

// ---------------- scratch ----------------------------------------------------
__device__ __align__(16) float g_xln[NT * CD];
__device__ __align__(16) float g_r[NT * CD];
__device__ __align__(16) float g_a[NT * CD];
__device__ float g_scale[NT];
__device__ int g_cnt[3];
__device__ int g_list[3 * NT];
__device__ int g_winner[NT];
__device__ float g_conf3[3 * NT];
__device__ int g_rc_cnt;
__device__ int g_rc_list[RC_CAP];
__device__ __align__(16) __half g_xh[NT * CD];
__device__ __align__(16) __half g_hh[NT * CD];
__device__ __align__(16) __half g_sh[NT * CD];
__device__ __align__(16) __half g_ah[NT * CD];
__device__ __align__(16) __half g_hr0[NT * HD];
__device__ __align__(16) __half g_hr1[NT * HD];
#define WSZ (23u * 1048576u)
__device__ __align__(16) __half g_wt[WSZ];

// ---------------- helpers ----------------------------------------------------
__device__ __forceinline__ uint32_t smem_u32(const void* p) {
    uint32_t a;
    asm("{ .reg .u64 t; cvta.to.shared.u64 t, %1; cvt.u32.u64 %0, t; }" : "=r"(a) : "l"(p));
    return a;
}
__device__ __forceinline__ void ldsm4(uint32_t* r, uint32_t a) {
    asm volatile("ldmatrix.sync.aligned.m8n8.x4.shared.b16 {%0,%1,%2,%3}, [%4];"
                 : "=r"(r[0]), "=r"(r[1]), "=r"(r[2]), "=r"(r[3]) : "r"(a));
}
__device__ __forceinline__ void mma16816(float* d, const uint32_t* a, const uint32_t* b) {
    asm volatile("mma.sync.aligned.m16n8k16.row.col.f32.f16.f16.f32 "
                 "{%0,%1,%2,%3}, {%4,%5,%6,%7}, {%8,%9}, {%0,%1,%2,%3};"
                 : "+f"(d[0]), "+f"(d[1]), "+f"(d[2]), "+f"(d[3])
                 : "r"(a[0]), "r"(a[1]), "r"(a[2]), "r"(a[3]), "r"(b[0]), "r"(b[1]));
}
__device__ __forceinline__ void cpa16(uint32_t s, const void* g) {
    asm volatile("cp.async.ca.shared.global [%0], [%1], 16;" :: "r"(s), "l"(g));
}
__device__ __forceinline__ float sigf(float x) { return 1.0f / (1.0f + expf(-x)); }
__device__ __forceinline__ unsigned packh(__half a, __half b) {
    return (unsigned)__half_as_ushort(a) | ((unsigned)__half_as_ushort(b) << 16);
}

// ================= HMMA tensor GEMM core (single fp16) ========================
enum { TEPI_HR = 0, TEPI_STORE = 1, TEPI_GATE = 2, TEPI_SCATTER = 3,
       TEPI_CVT = 4, TEPI_GATE2 = 5, TEPI_ADDX = 6 };
// per buffer: A 16KB @0, B 16KB @16384; 2 buffers (round-11 proven config)
#define TG_SMEM (2 * 32768 + 1024)

struct GDesc {
    const __half *Ah, *Bh;
    const int* Mptr;
    const int* gidx;
    const float* aux;
    const int* sidx;
    const float* scl;
    float* outF;
    __half* outH;
    int K, ldo, Nb;
};

__device__ __forceinline__ void tg_main(
    const __half* __restrict__ Ah, const __half* __restrict__ Bh,
    int M, int bm, int bn, int K, const int* __restrict__ gidx,
    uint32_t smb, float acc[4][4][4]) {
    int tid = threadIdx.x, lane = tid & 31, warp = tid >> 5;
    int wm = warp & 1, wn = warp >> 1;
    int quad = lane >> 3, r8 = lane & 7;

    uint32_t baseA[4], maskA[4];
    uint32_t kqA = (uint32_t)(quad >> 1) * 16;
#pragma unroll
    for (int mt = 0; mt < 4; mt++) {
        int rowA = wm * 64 + mt * 16 + (quad & 1) * 8 + r8;
        baseA[mt] = (uint32_t)rowA * 128;
        maskA[mt] = (uint32_t)(rowA & 7) << 4;
    }
    uint32_t baseB[2], maskB[2];
    uint32_t kqB = (uint32_t)(quad & 1) * 16;
#pragma unroll
    for (int n2 = 0; n2 < 2; n2++) {
        int rowB = wn * 32 + n2 * 16 + (quad >> 1) * 8 + r8;
        baseB[n2] = 16384u + (uint32_t)rowB * 128;
        maskB[n2] = (uint32_t)(rowB & 7) << 4;
    }

    int row = tid >> 1, h = tid & 1;
    int ra = bm + row; if (ra > M - 1) ra = M - 1;
    if (gidx) ra = gidx[ra];
    const __half* pA = Ah + (size_t)ra * K + h * 32;
    const __half* pB = Bh + (size_t)(bn + row) * K + h * 32;
    uint32_t mk = (uint32_t)(row & 7) << 4;
    uint32_t st[4];
#pragma unroll
    for (int i = 0; i < 4; i++)
        st[i] = (uint32_t)row * 128 + (((uint32_t)h * 64 + i * 16) ^ mk);

    auto stage = [&](int t, int buf) {
        int kc = t * 64;
        uint32_t ab = smb + (uint32_t)buf * 32768u;
#pragma unroll
        for (int i = 0; i < 4; i++) {
            cpa16(ab + st[i],          pA + kc + i * 8);
            cpa16(ab + 16384u + st[i], pB + kc + i * 8);
        }
        asm volatile("cp.async.commit_group;" ::: "memory");
    };

#pragma unroll
    for (int i = 0; i < 4; i++)
#pragma unroll
        for (int j = 0; j < 4; j++)
#pragma unroll
            for (int q = 0; q < 4; q++) acc[i][j][q] = 0.f;

    int nch = K >> 6;
    stage(0, 0);
    stage(1, 1);
    for (int t = 0; t < nch; t++) {
        if (t + 1 < nch) asm volatile("cp.async.wait_group 1;" ::: "memory");
        else             asm volatile("cp.async.wait_group 0;" ::: "memory");
        __syncthreads();
        uint32_t bufs = smb + (uint32_t)(t & 1) * 32768u;
#pragma unroll
        for (int ks = 0; ks < 4; ks++) {
            uint32_t cb = (uint32_t)ks * 32;
            uint32_t bfr[4][2];
#pragma unroll
            for (int n2 = 0; n2 < 2; n2++) {
                uint32_t r[4];
                ldsm4(r, bufs + baseB[n2] + ((kqB + cb) ^ maskB[n2]));
                bfr[2 * n2][0] = r[0]; bfr[2 * n2][1] = r[1];
                bfr[2 * n2 + 1][0] = r[2]; bfr[2 * n2 + 1][1] = r[3];
            }
#pragma unroll
            for (int mt = 0; mt < 4; mt++) {
                uint32_t a[4];
                ldsm4(a, bufs + baseA[mt] + ((kqA + cb) ^ maskA[mt]));
#pragma unroll
                for (int nt = 0; nt < 4; nt++)
                    mma16816(acc[mt][nt], a, bfr[nt]);
            }
        }
        __syncthreads();
        if (t + 2 < nch) stage(t + 2, t & 1);
    }
}

template <int EPI>
__device__ __forceinline__ void emit2(int grow, int gcol, float v0, float v1, int M,
                                      const float* __restrict__ aux,
                                      const int* __restrict__ sidx, const float* __restrict__ scl,
                                      float* __restrict__ outF, __half* __restrict__ outH, int ldo) {
    if (grow >= M) return;
    if (EPI == TEPI_STORE) {
        *(float2*)(outF + (size_t)grow * ldo + gcol) = make_float2(v0, v1);
    } else if (EPI == TEPI_ADDX) {
        float2 a = *(const float2*)(aux + (size_t)grow * CD + gcol);
        *(float2*)(outF + (size_t)grow * ldo + gcol) = make_float2(v0 + a.x, v1 + a.y);
    } else if (EPI == TEPI_SCATTER) {
        int orow = sidx[grow];
        float sc = scl[orow];
        float2* p = (float2*)(outF + (size_t)orow * ldo + gcol);
        float2 c = *p;
        c.x += v0 * sc; c.y += v1 * sc;
        *p = c;
    } else {
        if (EPI == TEPI_HR) {
            v0 = fmaxf(v0, 0.f); v0 *= v0;
            v1 = fmaxf(v1, 0.f); v1 *= v1;
        } else if (EPI == TEPI_GATE) {
            float2 a = *(const float2*)(aux + (size_t)grow * CD + gcol);
            v0 = a.x * sigf(v0); v1 = a.y * sigf(v1);
        } else if (EPI == TEPI_GATE2) {
            float2 a = *(const float2*)(aux + (size_t)grow * CD + gcol);
            v0 = sigf(a.x) * v0; v1 = sigf(a.y) * v1;
        }
        *(unsigned*)(outH + (size_t)grow * ldo + gcol) =
            packh(__float2half_rn(v0), __float2half_rn(v1));
    }
}

template <int EPI>
__device__ __forceinline__ void tg_epi(int M, int bm, int bn, float acc[4][4][4],
                                       const float* aux, const int* sidx, const float* scl,
                                       float* outF, __half* outH, int ldo) {
    int lane = threadIdx.x & 31, warp = threadIdx.x >> 5;
    int wm = warp & 1, wn = warp >> 1;
    int erow = lane >> 2, ecol = (lane & 3) * 2;
#pragma unroll
    for (int mt = 0; mt < 4; mt++) {
        int gr = bm + wm * 64 + mt * 16 + erow;
#pragma unroll
        for (int nt = 0; nt < 4; nt++) {
            int gc = bn + wn * 32 + nt * 8 + ecol;
            emit2<EPI>(gr,     gc, acc[mt][nt][0], acc[mt][nt][1], M, aux, sidx, scl, outF, outH, ldo);
            emit2<EPI>(gr + 8, gc, acc[mt][nt][2], acc[mt][nt][3], M, aux, sidx, scl, outF, outH, ldo);
        }
    }
}

template <int EPI>
__global__ void __launch_bounds__(256, 2)
tgemm(const __half* __restrict__ Ah, const __half* __restrict__ Bh,
      int Mstat, const int* __restrict__ Mptr, int K,
      const int* __restrict__ gidx, const float* __restrict__ aux,
      const int* __restrict__ sidx, const float* __restrict__ scl,
      float* __restrict__ outF, __half* __restrict__ outH, int ldo) {
    int M = Mptr ? *Mptr : Mstat;
    int bm = blockIdx.x * 128;
    if (bm >= M) return;
    int bn = blockIdx.y * 128;
    extern __shared__ char smraw[];
    uint32_t smb0 = smem_u32(smraw);
    uint32_t smb = (smb0 + 1023u) & ~1023u;
    float acc[4][4][4];
    tg_main(Ah, Bh, M, bm, bn, K, gidx, smb, acc);
    tg_epi<EPI>(M, bm, bn, acc, aux, sidx, scl, outF, outH, ldo);
}

template <int E0, int E1, int E2, int E3>
__global__ void __launch_bounds__(256, 2)
btgemm(GDesc g0, GDesc g1, GDesc g2, GDesc g3) {
    int z = blockIdx.z;
    GDesc g = (z == 0) ? g0 : (z == 1) ? g1 : (z == 2) ? g2 : g3;
    if ((int)blockIdx.y >= g.Nb) return;
    int M = *g.Mptr;
    int bm = blockIdx.x * 128;
    if (bm >= M) return;
    int bn = blockIdx.y * 128;
    extern __shared__ char smraw[];
    uint32_t smb0 = smem_u32(smraw);
    uint32_t smb = (smb0 + 1023u) & ~1023u;
    float acc[4][4][4];
    tg_main(g.Ah, g.Bh, M, bm, bn, g.K, g.gidx, smb, acc);
    if (z == 0)      tg_epi<E0>(M, bm, bn, acc, g.aux, g.sidx, g.scl, g.outF, g.outH, g.ldo);
    else if (z == 1) tg_epi<E1>(M, bm, bn, acc, g.aux, g.sidx, g.scl, g.outF, g.outH, g.ldo);
    else if (z == 2) tg_epi<E2>(M, bm, bn, acc, g.aux, g.sidx, g.scl, g.outF, g.outH, g.ldo);
    else             tg_epi<E3>(M, bm, bn, acc, g.aux, g.sidx, g.scl, g.outF, g.outH, g.ldo);
}

// ======== batched transpose + convert: W[K,N] -> WT[N,K] (fp16) ===============
struct TSArgs {
    const float* W[8];
    __half* O[8];
    int K, N;
};
__global__ void tsplit_b(TSArgs a) {
    __shared__ float t[32][33];
    const float* W = a.W[blockIdx.z];
    __half* O = a.O[blockIdx.z];
    int K = a.K, N = a.N;
    int n0 = blockIdx.x * 32, k0 = blockIdx.y * 32;
    int tx = threadIdx.x, ty = threadIdx.y;
#pragma unroll
    for (int j = 0; j < 4; j++)
        t[ty + 8 * j][tx] = W[(size_t)(k0 + ty + 8 * j) * N + n0 + tx];
    __syncthreads();
#pragma unroll
    for (int j = 0; j < 4; j++) {
        float v = t[tx][ty + 8 * j];
        O[(size_t)(n0 + ty + 8 * j) * K + k0 + tx] = __float2half_rn(v);
    }
}

// ================= LN / routing ===============================================
__device__ __forceinline__ float blockReduceSum(float v) {
    __shared__ float sh[8];
#pragma unroll
    for (int o = 16; o > 0; o >>= 1) v += __shfl_down_sync(0xffffffffu, v, o);
    int w = threadIdx.x >> 5, l = threadIdx.x & 31;
    if (l == 0) sh[w] = v;
    __syncthreads();
    if (threadIdx.x < 8) {
        float r = sh[threadIdx.x];
#pragma unroll
        for (int o = 4; o > 0; o >>= 1) r += __shfl_down_sync(0x000000ffu, r, o);
        if (threadIdx.x == 0) sh[0] = r;
    }
    __syncthreads();
    float res = sh[0];
    __syncthreads();
    return res;
}

__global__ void ln_kernel(const float* __restrict__ x, const float* __restrict__ w,
                          const float* __restrict__ b, float* __restrict__ out,
                          __half* __restrict__ oh) {
    int row = blockIdx.x, tid = threadIdx.x;
    float4 v = ((const float4*)(x + (size_t)row * CD))[tid];
    float s = blockReduceSum(v.x + v.y + v.z + v.w);
    float mean = s * (1.0f / CD);
    float dx = v.x - mean, dy = v.y - mean, dz = v.z - mean, dw = v.w - mean;
    float s2 = blockReduceSum(dx * dx + dy * dy + dz * dz + dw * dw);
    float rstd = 1.0f / sqrtf(s2 * (1.0f / CD) + 1e-5f);
    float4 wv = ((const float4*)w)[tid], bv = ((const float4*)b)[tid];
    float4 o = make_float4(dx * rstd * wv.x + bv.x, dy * rstd * wv.y + bv.y,
                           dz * rstd * wv.z + bv.z, dw * rstd * wv.w + bv.w);
    ((float4*)(out + (size_t)row * CD))[tid] = o;
    ((uint2*)(oh + (size_t)row * CD))[tid] =
        make_uint2(packh(__float2half_rn(o.x), __float2half_rn(o.y)),
                   packh(__float2half_rn(o.z), __float2half_rn(o.w)));
}

__global__ void ln2_route_kernel(const float* __restrict__ x2, const float* __restrict__ w,
                                 const float* __restrict__ b, const float* __restrict__ conf_rwkv,
                                 const float* __restrict__ conf_trans, const float* __restrict__ w_diff,
                                 const float* __restrict__ W_aff, const float* __restrict__ capital,
                                 __half* __restrict__ hh,
                                 float* __restrict__ conf3, int* __restrict__ winner,
                                 int* __restrict__ rc_cnt, int* __restrict__ rc_list) {
    int row = blockIdx.x, tid = threadIdx.x;
    float4 v = ((const float4*)(x2 + (size_t)row * CD))[tid];
    float s = blockReduceSum(v.x + v.y + v.z + v.w);
    float mean = s * (1.0f / CD);
    float dx = v.x - mean, dy = v.y - mean, dz = v.z - mean, dw = v.w - mean;
    float s2 = blockReduceSum(dx * dx + dy * dy + dz * dz + dw * dw);
    float rstd = 1.0f / sqrtf(s2 * (1.0f / CD) + 1e-5f);
    float4 wv = ((const float4*)w)[tid], bv = ((const float4*)b)[tid];
    float4 o = make_float4(dx * rstd * wv.x + bv.x, dy * rstd * wv.y + bv.y,
                           dz * rstd * wv.z + bv.z, dw * rstd * wv.w + bv.w);
    ((uint2*)(hh + (size_t)row * CD))[tid] =
        make_uint2(packh(__float2half_rn(o.x), __float2half_rn(o.y)),
                   packh(__float2half_rn(o.z), __float2half_rn(o.w)));

    float p[7];
    float4 c0 = ((const float4*)conf_rwkv)[tid];
    float4 c1 = ((const float4*)(conf_rwkv + CD))[tid];
    float4 ct = ((const float4*)conf_trans)[tid];
    float4 wd = ((const float4*)w_diff)[tid];
    p[0] = o.x * c0.x + o.y * c0.y + o.z * c0.z + o.w * c0.w;
    p[1] = o.x * c1.x + o.y * c1.y + o.z * c1.z + o.w * c1.w;
    p[2] = o.x * ct.x + o.y * ct.y + o.z * ct.z + o.w * ct.w;
    p[3] = o.x * wd.x + o.y * wd.y + o.z * wd.z + o.w * wd.w;
    const float* wa = W_aff + (size_t)tid * 12;
#pragma unroll
    for (int e = 0; e < 3; e++)
        p[4 + e] = o.x * wa[e] + o.y * wa[3 + e] + o.z * wa[6 + e] + o.w * wa[9 + e];

    __shared__ float red[7][8];
    int wid = tid >> 5, lid = tid & 31;
#pragma unroll
    for (int q = 0; q < 7; q++) {
        float vv = p[q];
#pragma unroll
        for (int o2 = 16; o2 > 0; o2 >>= 1) vv += __shfl_down_sync(0xffffffffu, vv, o2);
        if (lid == 0) red[q][wid] = vv;
    }
    __syncthreads();
    if (tid == 0) {
        float d[7];
#pragma unroll
        for (int q = 0; q < 7; q++) {
            float t = 0.f;
#pragma unroll
            for (int k = 0; k < 8; k++) t += red[q][k];
            d[q] = t;
        }
        float cf[3] = {sigf(d[0]), sigf(d[1]), sigf(d[2])};
        float diff = sigf(d[3]);
        float bids[3];
#pragma unroll
        for (int e = 0; e < 3; e++) {
            bids[e] = cf[e] * capital[e] * diff + d[4 + e];
            conf3[row * 3 + e] = cf[e];
        }
        int wdx = 0; float best = bids[0];
        if (bids[1] > best) { best = bids[1]; wdx = 1; }
        if (bids[2] > best) { best = bids[2]; wdx = 2; }
        float second = -1e30f;
#pragma unroll
        for (int e = 0; e < 3; e++)
            if (e != wdx && bids[e] > second) second = bids[e];
        winner[row] = wdx;
        if (best - second < 1e-3f) {
            int pos = atomicAdd(rc_cnt, 1);
            if (pos < RC_CAP) rc_list[pos] = row;
        }
    }
}

// exact fp32 recompute of routing for marginal tokens (coalesced row-major GEMV)
__global__ void recheck_kernel(const float* __restrict__ x, const float* __restrict__ xln,
                               const float* __restrict__ Wr, const float* __restrict__ Wv,
                               const float* __restrict__ Wo,
                               const float* __restrict__ ln2w, const float* __restrict__ ln2b,
                               const float* __restrict__ conf_rwkv, const float* __restrict__ conf_trans,
                               const float* __restrict__ w_diff, const float* __restrict__ W_aff,
                               const float* __restrict__ capital,
                               const int* __restrict__ rc_cnt, const int* __restrict__ rc_list,
                               int* __restrict__ winner) {
    int n = *rc_cnt; if (n > RC_CAP) n = RC_CAP;
    int bi = blockIdx.x;
    if (bi >= n) return;
    int row = rc_list[bi];
    int tid = threadIdx.x;
    __shared__ float sx[CD];
    __shared__ float su[CD];
    for (int c = tid; c < CD; c += 256) sx[c] = xln[(size_t)row * CD + c];
    __syncthreads();

    float racc[4] = {0, 0, 0, 0}, vacc[4] = {0, 0, 0, 0};
    for (int k = 0; k < CD; k++) {
        float xv = sx[k];
        const float* wr = Wr + (size_t)k * CD + tid;
        const float* wv = Wv + (size_t)k * CD + tid;
#pragma unroll
        for (int j = 0; j < 4; j++) {
            racc[j] += xv * wr[j * 256];
            vacc[j] += xv * wv[j * 256];
        }
    }
#pragma unroll
    for (int j = 0; j < 4; j++)
        su[tid + j * 256] = sigf(racc[j]) * vacc[j];
    __syncthreads();

    float oacc[4] = {0, 0, 0, 0};
    for (int k = 0; k < CD; k++) {
        float uv = su[k];
        const float* wo = Wo + (size_t)k * CD + tid;
#pragma unroll
        for (int j = 0; j < 4; j++) oacc[j] += uv * wo[j * 256];
    }
    __syncthreads();
#pragma unroll
    for (int j = 0; j < 4; j++)
        sx[tid + j * 256] = oacc[j] + x[(size_t)row * CD + tid + j * 256];
    __syncthreads();

    float ps = 0.f;
    for (int c = tid; c < CD; c += 256) ps += sx[c];
    float mean = blockReduceSum(ps) * (1.0f / CD);
    float ps2 = 0.f;
    for (int c = tid; c < CD; c += 256) { float d = sx[c] - mean; ps2 += d * d; }
    float rstd = 1.0f / sqrtf(blockReduceSum(ps2) * (1.0f / CD) + 1e-5f);

    float p[7] = {0, 0, 0, 0, 0, 0, 0};
    for (int c = tid; c < CD; c += 256) {
        float hc = (sx[c] - mean) * rstd * ln2w[c] + ln2b[c];
        p[0] += hc * conf_rwkv[c];
        p[1] += hc * conf_rwkv[CD + c];
        p[2] += hc * conf_trans[c];
        p[3] += hc * w_diff[c];
        p[4] += hc * W_aff[c * 3 + 0];
        p[5] += hc * W_aff[c * 3 + 1];
        p[6] += hc * W_aff[c * 3 + 2];
    }
    __shared__ float red[7][8];
    int wid = tid >> 5, lid = tid & 31;
#pragma unroll
    for (int q = 0; q < 7; q++) {
        float vv = p[q];
#pragma unroll
        for (int o2 = 16; o2 > 0; o2 >>= 1) vv += __shfl_down_sync(0xffffffffu, vv, o2);
        if (lid == 0) red[q][wid] = vv;
    }
    __syncthreads();
    if (tid == 0) {
        float d[7];
#pragma unroll
        for (int q = 0; q < 7; q++) {
            float t = 0.f;
#pragma unroll
            for (int k = 0; k < 8; k++) t += red[q][k];
            d[q] = t;
        }
        float cf[3] = {sigf(d[0]), sigf(d[1]), sigf(d[2])};
        float diff = sigf(d[3]);
        int wdx = 0; float best = -1e30f;
#pragma unroll
        for (int e = 0; e < 3; e++) {
            float bid = cf[e] * capital[e] * diff + d[4 + e];
            if (bid > best) { best = bid; wdx = e; }
        }
        winner[row] = wdx;
    }
}

__global__ void build_lists(const int* __restrict__ winner, const float* __restrict__ conf3,
                            float* __restrict__ scale_out, int* __restrict__ cnt, int* __restrict__ lst) {
    int i = blockIdx.x * 256 + threadIdx.x;
    if (i >= NT) return;
    int w = winner[i];
    float wc = conf3[i * 3 + w];
    scale_out[i] = wc / (wc + 1e-6f);
    int pos = atomicAdd(&cnt[w], 1);
    lst[w * NT + pos] = i;
}

__global__ void zero_cnt_kernel(int* c, int* rc) {
    if (threadIdx.x < 3) c[threadIdx.x] = 0;
    if (threadIdx.x == 0) *rc = 0;
}

// ================= launch =====================================================
extern "C" void kernel_launch(void* const* d_in, const int* in_sizes, int n_in,
                              void* d_out, int out_size) {
    const float* x = (const float*)d_in[0];
    const float* capital = (const float*)d_in[2];
    const float* ln1w = (const float*)d_in[3], *ln1b = (const float*)d_in[4];
    const float* ln2w = (const float*)d_in[5], *ln2b = (const float*)d_in[6];
    const float* Wr = (const float*)d_in[7], *Wv = (const float*)d_in[8];
    const float* Wo = (const float*)d_in[9], *Ws = (const float*)d_in[10];
    const float* Kr = (const float*)d_in[11], *Vr = (const float*)d_in[12];
    const float* confr = (const float*)d_in[13];
    const float* W1 = (const float*)d_in[14], *W2 = (const float*)d_in[15];
    const float* W3 = (const float*)d_in[16];
    const float* conft = (const float*)d_in[17], *wdiff = (const float*)d_in[18];
    const float* Waff = (const float*)d_in[19];
    float* out = (float*)d_out;

    void* p;
    cudaGetSymbolAddress(&p, g_xln);    float* xln = (float*)p;
    cudaGetSymbolAddress(&p, g_r);      float* rb = (float*)p;
    cudaGetSymbolAddress(&p, g_a);      float* ab = (float*)p;
    cudaGetSymbolAddress(&p, g_scale);  float* sclp = (float*)p;
    cudaGetSymbolAddress(&p, g_cnt);    int* cnt = (int*)p;
    cudaGetSymbolAddress(&p, g_list);   int* lst = (int*)p;
    cudaGetSymbolAddress(&p, g_winner); int* win = (int*)p;
    cudaGetSymbolAddress(&p, g_conf3);  float* conf3 = (float*)p;
    cudaGetSymbolAddress(&p, g_rc_cnt); int* rc_cnt = (int*)p;
    cudaGetSymbolAddress(&p, g_rc_list);int* rc_list = (int*)p;
    cudaGetSymbolAddress(&p, g_xh);     __half* xh = (__half*)p;
    cudaGetSymbolAddress(&p, g_hh);     __half* hh = (__half*)p;
    cudaGetSymbolAddress(&p, g_sh);     __half* sh = (__half*)p;
    cudaGetSymbolAddress(&p, g_ah);     __half* ah = (__half*)p;
    cudaGetSymbolAddress(&p, g_hr0);    __half* hr0 = (__half*)p;
    cudaGetSymbolAddress(&p, g_hr1);    __half* hr1 = (__half*)p;
    cudaGetSymbolAddress(&p, g_wt);     __half* wt = (__half*)p;

    cudaFuncSetAttribute(tgemm<TEPI_STORE>,   cudaFuncAttributeMaxDynamicSharedMemorySize, TG_SMEM);
    cudaFuncSetAttribute(tgemm<TEPI_GATE2>,   cudaFuncAttributeMaxDynamicSharedMemorySize, TG_SMEM);
    cudaFuncSetAttribute(tgemm<TEPI_ADDX>,    cudaFuncAttributeMaxDynamicSharedMemorySize, TG_SMEM);
    cudaFuncSetAttribute(tgemm<TEPI_SCATTER>, cudaFuncAttributeMaxDynamicSharedMemorySize, TG_SMEM);
    cudaFuncSetAttribute((const void*)btgemm<TEPI_CVT, TEPI_STORE, TEPI_HR, TEPI_HR>,
                         cudaFuncAttributeMaxDynamicSharedMemorySize, TG_SMEM);
    cudaFuncSetAttribute((const void*)btgemm<TEPI_GATE, TEPI_SCATTER, TEPI_SCATTER, TEPI_SCATTER>,
                         cudaFuncAttributeMaxDynamicSharedMemorySize, TG_SMEM);

    const size_t M1 = 1048576;
    const size_t KR0T = 0, KR1T = 4 * M1, VR0T = 8 * M1, VR1T = 12 * M1;
    const size_t W1T = 16 * M1, W2T = 17 * M1, W3T = 18 * M1;
    const size_t WRT = 19 * M1, WVT = 20 * M1, WOT = 21 * M1, WST = 22 * M1;

    dim3 blk(256), tb(32, 8);
    dim3 gC(NT / 128, CD / 128);

    // weight transpose+convert (fp16), batched: 3 launches
    {
        TSArgs a{};
        a.W[0] = W1; a.O[0] = wt + W1T;
        a.W[1] = W2; a.O[1] = wt + W2T;
        a.W[2] = W3; a.O[2] = wt + W3T;
        a.W[3] = Wr; a.O[3] = wt + WRT;
        a.W[4] = Wv; a.O[4] = wt + WVT;
        a.W[5] = Wo; a.O[5] = wt + WOT;
        a.W[6] = Ws; a.O[6] = wt + WST;
        a.K = CD; a.N = CD;
        tsplit_b<<<dim3(CD / 32, CD / 32, 7), tb>>>(a);
    }
    {
        TSArgs a{};
        a.W[0] = Kr;                     a.O[0] = wt + KR0T;
        a.W[1] = Kr + (size_t)CD * HD;   a.O[1] = wt + KR1T;
        a.K = CD; a.N = HD;
        tsplit_b<<<dim3(HD / 32, CD / 32, 2), tb>>>(a);
    }
    {
        TSArgs a{};
        a.W[0] = Vr;                     a.O[0] = wt + VR0T;
        a.W[1] = Vr + (size_t)HD * CD;   a.O[1] = wt + VR1T;
        a.K = HD; a.N = CD;
        tsplit_b<<<dim3(CD / 32, HD / 32, 2), tb>>>(a);
    }

    zero_cnt_kernel<<<1, 32>>>(cnt, rc_cnt);
    ln_kernel<<<NT, 256>>>(x, ln1w, ln1b, xln, xh);

    // attention path: single-fp16 HMMA
    tgemm<TEPI_STORE><<<gC, blk, TG_SMEM>>>(xh, wt + WRT, NT, nullptr, CD,
                                            nullptr, nullptr, nullptr, nullptr, rb, nullptr, CD);
    tgemm<TEPI_GATE2><<<gC, blk, TG_SMEM>>>(xh, wt + WVT, NT, nullptr, CD,
                                            nullptr, rb, nullptr, nullptr, nullptr, ah, CD);
    tgemm<TEPI_ADDX><<<gC, blk, TG_SMEM>>>(ah, wt + WOT, NT, nullptr, CD,
                                           nullptr, x, nullptr, nullptr, out, nullptr, CD);

    // routing (provisional, flags marginal tokens) -> exact recheck -> lists
    ln2_route_kernel<<<NT, 256>>>(out, ln2w, ln2b, confr, conft, wdiff, Waff, capital,
                                  hh, conf3, win, rc_cnt, rc_list);
    recheck_kernel<<<RC_CAP, 256>>>(x, xln, Wr, Wv, Wo, ln2w, ln2b, confr, conft, wdiff,
                                    Waff, capital, rc_cnt, rc_list, win);
    build_lists<<<NT / 256, 256>>>(win, conf3, sclp, cnt, lst);

    // ---- batched expert set 1: {Ws(sparse,cvt), W1, K0, K1} ----
    GDesc dws = {xh, wt + WST, cnt + 2, lst + 2 * NT,
                 nullptr, nullptr, nullptr, nullptr, sh, CD, CD, 8};
    GDesc dw1 = {hh, wt + W1T, cnt + 2, lst + 2 * NT,
                 nullptr, nullptr, nullptr, ab, nullptr, CD, CD, 8};
    GDesc dk0 = {hh, wt + KR0T, cnt + 0, lst + 0 * NT,
                 nullptr, nullptr, nullptr, nullptr, hr0, CD, HD, 32};
    GDesc dk1 = {hh, wt + KR1T, cnt + 1, lst + 1 * NT,
                 nullptr, nullptr, nullptr, nullptr, hr1, CD, HD, 32};
    btgemm<TEPI_CVT, TEPI_STORE, TEPI_HR, TEPI_HR>
        <<<dim3(NT / 128, 32, 4), blk, TG_SMEM>>>(dws, dw1, dk0, dk1);

    // ---- batched expert set 2: {W2(gate), V0, V1} ----
    GDesc dw2 = {sh, wt + W2T, cnt + 2, nullptr,
                 ab, nullptr, nullptr, nullptr, ah, CD, CD, 8};
    GDesc dv0 = {hr0, wt + VR0T, cnt + 0, nullptr,
                 nullptr, lst + 0 * NT, sclp, out, nullptr, HD, CD, 8};
    GDesc dv1 = {hr1, wt + VR1T, cnt + 1, nullptr,
                 nullptr, lst + 1 * NT, sclp, out, nullptr, HD, CD, 8};
    btgemm<TEPI_GATE, TEPI_SCATTER, TEPI_SCATTER, TEPI_SCATTER>
        <<<dim3(NT / 128, 8, 3), blk, TG_SMEM>>>(dw2, dv0, dv1, dv1);

    // ---- set 3: W3 (scatter) ----
    tgemm<TEPI_SCATTER><<<gC, blk, TG_SMEM>>>(ah, wt + W3T, 0, cnt + 2, CD,
                                              nullptr, nullptr, lst + 2 * NT, sclp, out, nullptr, CD);
}

// round 14
// speedup vs baseline: 1.1144x; 1.0409x over previous
#include <cuda_runtime.h>
#include <cuda_fp16.h>
#include <math.h>
#include <stdint.h>

#define NT 8192
#define CD 1024
#define HD 4096
#define RC_CAP 512

// ---------------- scratch ----------------------------------------------------
__device__ __align__(16) float g_xln[NT * CD];
__device__ __align__(16) float g_a[NT * CD];
__device__ float g_scale[NT];
__device__ int g_cnt[3];
__device__ int g_list[3 * NT];
__device__ int g_winner[NT];
__device__ float g_conf3[3 * NT];
__device__ int g_rc_cnt;
__device__ int g_rc_list[RC_CAP];
__device__ __align__(16) __half g_xh[NT * CD];
__device__ __align__(16) __half g_hh[NT * CD];
__device__ __align__(16) __half g_sh[NT * CD];
__device__ __align__(16) __half g_ah[NT * CD];
__device__ __align__(16) __half g_hr0[NT * HD];
__device__ __align__(16) __half g_hr1[NT * HD];
#define WSZ (23u * 1048576u)
__device__ __align__(16) __half g_wt[WSZ];

// ---------------- helpers ----------------------------------------------------
__device__ __forceinline__ uint32_t smem_u32(const void* p) {
    uint32_t a;
    asm("{ .reg .u64 t; cvta.to.shared.u64 t, %1; cvt.u32.u64 %0, t; }" : "=r"(a) : "l"(p));
    return a;
}
__device__ __forceinline__ void ldsm4(uint32_t* r, uint32_t a) {
    asm volatile("ldmatrix.sync.aligned.m8n8.x4.shared.b16 {%0,%1,%2,%3}, [%4];"
                 : "=r"(r[0]), "=r"(r[1]), "=r"(r[2]), "=r"(r[3]) : "r"(a));
}
__device__ __forceinline__ void mma16816(float* d, const uint32_t* a, const uint32_t* b) {
    asm volatile("mma.sync.aligned.m16n8k16.row.col.f32.f16.f16.f32 "
                 "{%0,%1,%2,%3}, {%4,%5,%6,%7}, {%8,%9}, {%0,%1,%2,%3};"
                 : "+f"(d[0]), "+f"(d[1]), "+f"(d[2]), "+f"(d[3])
                 : "r"(a[0]), "r"(a[1]), "r"(a[2]), "r"(a[3]), "r"(b[0]), "r"(b[1]));
}
__device__ __forceinline__ void cpa16(uint32_t s, const void* g) {
    asm volatile("cp.async.ca.shared.global [%0], [%1], 16;" :: "r"(s), "l"(g));
}
__device__ __forceinline__ float sigf(float x) { return 1.0f / (1.0f + expf(-x)); }
__device__ __forceinline__ unsigned packh(__half a, __half b) {
    return (unsigned)__half_as_ushort(a) | ((unsigned)__half_as_ushort(b) << 16);
}

// ================= HMMA tensor GEMM core (single fp16) ========================
enum { TEPI_HR = 0, TEPI_STORE = 1, TEPI_GATE = 2, TEPI_SCATTER = 3,
       TEPI_CVT = 4, TEPI_ADDX = 6 };
// per buffer: A 16KB @0, B 16KB @16384; 2 buffers
#define TG_SMEM (2 * 32768 + 1024)

struct GDesc {
    const __half *Ah, *Bh;
    const int* Mptr;
    const int* gidx;
    const float* aux;
    const int* sidx;
    const float* scl;
    float* outF;
    __half* outH;
    int K, ldo, Nb;
};

__device__ __forceinline__ void tg_main(
    const __half* __restrict__ Ah, const __half* __restrict__ Bh,
    int M, int bm, int bn, int K, const int* __restrict__ gidx,
    uint32_t smb, float acc[4][4][4]) {
    int tid = threadIdx.x, lane = tid & 31, warp = tid >> 5;
    int wm = warp & 1, wn = warp >> 1;
    int quad = lane >> 3, r8 = lane & 7;

    uint32_t baseA[4], maskA[4];
    uint32_t kqA = (uint32_t)(quad >> 1) * 16;
#pragma unroll
    for (int mt = 0; mt < 4; mt++) {
        int rowA = wm * 64 + mt * 16 + (quad & 1) * 8 + r8;
        baseA[mt] = (uint32_t)rowA * 128;
        maskA[mt] = (uint32_t)(rowA & 7) << 4;
    }
    uint32_t baseB[2], maskB[2];
    uint32_t kqB = (uint32_t)(quad & 1) * 16;
#pragma unroll
    for (int n2 = 0; n2 < 2; n2++) {
        int rowB = wn * 32 + n2 * 16 + (quad >> 1) * 8 + r8;
        baseB[n2] = 16384u + (uint32_t)rowB * 128;
        maskB[n2] = (uint32_t)(rowB & 7) << 4;
    }

    int row = tid >> 1, h = tid & 1;
    int ra = bm + row; if (ra > M - 1) ra = M - 1;
    if (gidx) ra = gidx[ra];
    const __half* pA = Ah + (size_t)ra * K + h * 32;
    const __half* pB = Bh + (size_t)(bn + row) * K + h * 32;
    uint32_t mk = (uint32_t)(row & 7) << 4;
    uint32_t st[4];
#pragma unroll
    for (int i = 0; i < 4; i++)
        st[i] = (uint32_t)row * 128 + (((uint32_t)h * 64 + i * 16) ^ mk);

    auto stage = [&](int t, int buf) {
        int kc = t * 64;
        uint32_t ab = smb + (uint32_t)buf * 32768u;
#pragma unroll
        for (int i = 0; i < 4; i++) {
            cpa16(ab + st[i],          pA + kc + i * 8);
            cpa16(ab + 16384u + st[i], pB + kc + i * 8);
        }
        asm volatile("cp.async.commit_group;" ::: "memory");
    };

#pragma unroll
    for (int i = 0; i < 4; i++)
#pragma unroll
        for (int j = 0; j < 4; j++)
#pragma unroll
            for (int q = 0; q < 4; q++) acc[i][j][q] = 0.f;

    int nch = K >> 6;
    stage(0, 0);
    stage(1, 1);
    for (int t = 0; t < nch; t++) {
        if (t + 1 < nch) asm volatile("cp.async.wait_group 1;" ::: "memory");
        else             asm volatile("cp.async.wait_group 0;" ::: "memory");
        __syncthreads();
        uint32_t bufs = smb + (uint32_t)(t & 1) * 32768u;
#pragma unroll
        for (int ks = 0; ks < 4; ks++) {
            uint32_t cb = (uint32_t)ks * 32;
            uint32_t bfr[4][2];
#pragma unroll
            for (int n2 = 0; n2 < 2; n2++) {
                uint32_t r[4];
                ldsm4(r, bufs + baseB[n2] + ((kqB + cb) ^ maskB[n2]));
                bfr[2 * n2][0] = r[0]; bfr[2 * n2][1] = r[1];
                bfr[2 * n2 + 1][0] = r[2]; bfr[2 * n2 + 1][1] = r[3];
            }
#pragma unroll
            for (int mt = 0; mt < 4; mt++) {
                uint32_t a[4];
                ldsm4(a, bufs + baseA[mt] + ((kqA + cb) ^ maskA[mt]));
#pragma unroll
                for (int nt = 0; nt < 4; nt++)
                    mma16816(acc[mt][nt], a, bfr[nt]);
            }
        }
        __syncthreads();
        if (t + 2 < nch) stage(t + 2, t & 1);
    }
}

template <int EPI>
__device__ __forceinline__ void emit2(int grow, int gcol, float v0, float v1, int M,
                                      const float* __restrict__ aux,
                                      const int* __restrict__ sidx, const float* __restrict__ scl,
                                      float* __restrict__ outF, __half* __restrict__ outH, int ldo) {
    if (grow >= M) return;
    if (EPI == TEPI_STORE) {
        *(float2*)(outF + (size_t)grow * ldo + gcol) = make_float2(v0, v1);
    } else if (EPI == TEPI_ADDX) {
        float2 a = *(const float2*)(aux + (size_t)grow * CD + gcol);
        *(float2*)(outF + (size_t)grow * ldo + gcol) = make_float2(v0 + a.x, v1 + a.y);
    } else if (EPI == TEPI_SCATTER) {
        int orow = sidx[grow];
        float sc = scl[orow];
        float2* p = (float2*)(outF + (size_t)orow * ldo + gcol);
        float2 c = *p;
        c.x += v0 * sc; c.y += v1 * sc;
        *p = c;
    } else {
        if (EPI == TEPI_HR) {
            v0 = fmaxf(v0, 0.f); v0 *= v0;
            v1 = fmaxf(v1, 0.f); v1 *= v1;
        } else if (EPI == TEPI_GATE) {
            float2 a = *(const float2*)(aux + (size_t)grow * CD + gcol);
            v0 = a.x * sigf(v0); v1 = a.y * sigf(v1);
        }
        *(unsigned*)(outH + (size_t)grow * ldo + gcol) =
            packh(__float2half_rn(v0), __float2half_rn(v1));
    }
}

template <int EPI>
__device__ __forceinline__ void tg_epi(int M, int bm, int bn, float acc[4][4][4],
                                       const float* aux, const int* sidx, const float* scl,
                                       float* outF, __half* outH, int ldo) {
    int lane = threadIdx.x & 31, warp = threadIdx.x >> 5;
    int wm = warp & 1, wn = warp >> 1;
    int erow = lane >> 2, ecol = (lane & 3) * 2;
#pragma unroll
    for (int mt = 0; mt < 4; mt++) {
        int gr = bm + wm * 64 + mt * 16 + erow;
#pragma unroll
        for (int nt = 0; nt < 4; nt++) {
            int gc = bn + wn * 32 + nt * 8 + ecol;
            emit2<EPI>(gr,     gc, acc[mt][nt][0], acc[mt][nt][1], M, aux, sidx, scl, outF, outH, ldo);
            emit2<EPI>(gr + 8, gc, acc[mt][nt][2], acc[mt][nt][3], M, aux, sidx, scl, outF, outH, ldo);
        }
    }
}

template <int EPI>
__global__ void __launch_bounds__(256, 2)
tgemm(const __half* __restrict__ Ah, const __half* __restrict__ Bh,
      int Mstat, const int* __restrict__ Mptr, int K,
      const int* __restrict__ gidx, const float* __restrict__ aux,
      const int* __restrict__ sidx, const float* __restrict__ scl,
      float* __restrict__ outF, __half* __restrict__ outH, int ldo) {
    int M = Mptr ? *Mptr : Mstat;
    int bm = blockIdx.x * 128;
    if (bm >= M) return;
    int bn = blockIdx.y * 128;
    extern __shared__ char smraw[];
    uint32_t smb0 = smem_u32(smraw);
    uint32_t smb = (smb0 + 1023u) & ~1023u;
    float acc[4][4][4];
    tg_main(Ah, Bh, M, bm, bn, K, gidx, smb, acc);
    tg_epi<EPI>(M, bm, bn, acc, aux, sidx, scl, outF, outH, ldo);
}

template <int E0, int E1, int E2, int E3>
__global__ void __launch_bounds__(256, 2)
btgemm(GDesc g0, GDesc g1, GDesc g2, GDesc g3) {
    int z = blockIdx.z;
    GDesc g = (z == 0) ? g0 : (z == 1) ? g1 : (z == 2) ? g2 : g3;
    if ((int)blockIdx.y >= g.Nb) return;
    int M = *g.Mptr;
    int bm = blockIdx.x * 128;
    if (bm >= M) return;
    int bn = blockIdx.y * 128;
    extern __shared__ char smraw[];
    uint32_t smb0 = smem_u32(smraw);
    uint32_t smb = (smb0 + 1023u) & ~1023u;
    float acc[4][4][4];
    tg_main(g.Ah, g.Bh, M, bm, bn, g.K, g.gidx, smb, acc);
    if (z == 0)      tg_epi<E0>(M, bm, bn, acc, g.aux, g.sidx, g.scl, g.outF, g.outH, g.ldo);
    else if (z == 1) tg_epi<E1>(M, bm, bn, acc, g.aux, g.sidx, g.scl, g.outF, g.outH, g.ldo);
    else if (z == 2) tg_epi<E2>(M, bm, bn, acc, g.aux, g.sidx, g.scl, g.outF, g.outH, g.ldo);
    else             tg_epi<E3>(M, bm, bn, acc, g.aux, g.sidx, g.scl, g.outF, g.outH, g.ldo);
}

// ====== fused Wr+Wv attention kernel: ah = sigmoid(x@Wr) * (x@Wv), fp16 out ===
// B tile = [64 rows WrT ; 64 rows WvT]; each warp holds matching r/v fragments.
__global__ void __launch_bounds__(256, 2)
tgemm_rv(const __half* __restrict__ Ah,
         const __half* __restrict__ Br, const __half* __restrict__ Bv,
         int K, __half* __restrict__ outH, int ldo) {
    int bm = blockIdx.x * 128;
    int bn = blockIdx.y * 64;
    extern __shared__ char smraw[];
    uint32_t smb0 = smem_u32(smraw);
    uint32_t smb = (smb0 + 1023u) & ~1023u;

    int tid = threadIdx.x, lane = tid & 31, warp = tid >> 5;
    int wm = warp & 1, wn = warp >> 1;   // 4 col-groups of 16
    int quad = lane >> 3, r8 = lane & 7;

    uint32_t baseA[4], maskA[4];
    uint32_t kqA = (uint32_t)(quad >> 1) * 16;
#pragma unroll
    for (int mt = 0; mt < 4; mt++) {
        int rowA = wm * 64 + mt * 16 + (quad & 1) * 8 + r8;
        baseA[mt] = (uint32_t)rowA * 128;
        maskA[mt] = (uint32_t)(rowA & 7) << 4;
    }
    uint32_t kqB = (uint32_t)(quad & 1) * 16;
    int rowBr = wn * 16 + (quad >> 1) * 8 + r8;
    uint32_t baseBr = 16384u + (uint32_t)rowBr * 128;
    uint32_t maskBr = (uint32_t)(rowBr & 7) << 4;
    int rowBv = rowBr + 64;
    uint32_t baseBv = 16384u + (uint32_t)rowBv * 128;
    uint32_t maskBv = (uint32_t)(rowBv & 7) << 4;

    int row = tid >> 1, h = tid & 1;
    const __half* pA = Ah + (size_t)(bm + row) * K + h * 32;
    const __half* pB = (row < 64 ? Br + (size_t)(bn + row) * K
                                 : Bv + (size_t)(bn + row - 64) * K) + h * 32;
    uint32_t mk = (uint32_t)(row & 7) << 4;
    uint32_t st[4];
#pragma unroll
    for (int i = 0; i < 4; i++)
        st[i] = (uint32_t)row * 128 + (((uint32_t)h * 64 + i * 16) ^ mk);

    auto stage = [&](int t, int buf) {
        int kc = t * 64;
        uint32_t ab = smb + (uint32_t)buf * 32768u;
#pragma unroll
        for (int i = 0; i < 4; i++) {
            cpa16(ab + st[i],          pA + kc + i * 8);
            cpa16(ab + 16384u + st[i], pB + kc + i * 8);
        }
        asm volatile("cp.async.commit_group;" ::: "memory");
    };

    float accR[4][2][4], accV[4][2][4];
#pragma unroll
    for (int i = 0; i < 4; i++)
#pragma unroll
        for (int j = 0; j < 2; j++)
#pragma unroll
            for (int q = 0; q < 4; q++) { accR[i][j][q] = 0.f; accV[i][j][q] = 0.f; }

    int nch = K >> 6;
    stage(0, 0);
    stage(1, 1);
    for (int t = 0; t < nch; t++) {
        if (t + 1 < nch) asm volatile("cp.async.wait_group 1;" ::: "memory");
        else             asm volatile("cp.async.wait_group 0;" ::: "memory");
        __syncthreads();
        uint32_t bufs = smb + (uint32_t)(t & 1) * 32768u;
#pragma unroll
        for (int ks = 0; ks < 4; ks++) {
            uint32_t cb = (uint32_t)ks * 32;
            uint32_t br[2][2], bv[2][2], r4[4];
            ldsm4(r4, bufs + baseBr + ((kqB + cb) ^ maskBr));
            br[0][0] = r4[0]; br[0][1] = r4[1]; br[1][0] = r4[2]; br[1][1] = r4[3];
            ldsm4(r4, bufs + baseBv + ((kqB + cb) ^ maskBv));
            bv[0][0] = r4[0]; bv[0][1] = r4[1]; bv[1][0] = r4[2]; bv[1][1] = r4[3];
#pragma unroll
            for (int mt = 0; mt < 4; mt++) {
                uint32_t a[4];
                ldsm4(a, bufs + baseA[mt] + ((kqA + cb) ^ maskA[mt]));
#pragma unroll
                for (int nt = 0; nt < 2; nt++) {
                    mma16816(accR[mt][nt], a, br[nt]);
                    mma16816(accV[mt][nt], a, bv[nt]);
                }
            }
        }
        __syncthreads();
        if (t + 2 < nch) stage(t + 2, t & 1);
    }

    int erow = lane >> 2, ecol = (lane & 3) * 2;
#pragma unroll
    for (int mt = 0; mt < 4; mt++) {
        int gr = bm + wm * 64 + mt * 16 + erow;
#pragma unroll
        for (int nt = 0; nt < 2; nt++) {
            int gc = bn + wn * 16 + nt * 8 + ecol;
            float g0 = sigf(accR[mt][nt][0]) * accV[mt][nt][0];
            float g1 = sigf(accR[mt][nt][1]) * accV[mt][nt][1];
            *(unsigned*)(outH + (size_t)gr * ldo + gc) =
                packh(__float2half_rn(g0), __float2half_rn(g1));
            float g2 = sigf(accR[mt][nt][2]) * accV[mt][nt][2];
            float g3 = sigf(accR[mt][nt][3]) * accV[mt][nt][3];
            *(unsigned*)(outH + (size_t)(gr + 8) * ldo + gc) =
                packh(__float2half_rn(g2), __float2half_rn(g3));
        }
    }
}

// ======== batched transpose + convert: W[K,N] -> WT[N,K] (fp16) ===============
struct TSArgs {
    const float* W[8];
    __half* O[8];
    int K, N;
};
__global__ void tsplit_b(TSArgs a) {
    __shared__ float t[32][33];
    const float* W = a.W[blockIdx.z];
    __half* O = a.O[blockIdx.z];
    int K = a.K, N = a.N;
    int n0 = blockIdx.x * 32, k0 = blockIdx.y * 32;
    int tx = threadIdx.x, ty = threadIdx.y;
#pragma unroll
    for (int j = 0; j < 4; j++)
        t[ty + 8 * j][tx] = W[(size_t)(k0 + ty + 8 * j) * N + n0 + tx];
    __syncthreads();
#pragma unroll
    for (int j = 0; j < 4; j++) {
        float v = t[tx][ty + 8 * j];
        O[(size_t)(n0 + ty + 8 * j) * K + k0 + tx] = __float2half_rn(v);
    }
}

// ================= LN / routing ===============================================
__device__ __forceinline__ float blockReduceSum(float v) {
    __shared__ float sh[8];
#pragma unroll
    for (int o = 16; o > 0; o >>= 1) v += __shfl_down_sync(0xffffffffu, v, o);
    int w = threadIdx.x >> 5, l = threadIdx.x & 31;
    if (l == 0) sh[w] = v;
    __syncthreads();
    if (threadIdx.x < 8) {
        float r = sh[threadIdx.x];
#pragma unroll
        for (int o = 4; o > 0; o >>= 1) r += __shfl_down_sync(0x000000ffu, r, o);
        if (threadIdx.x == 0) sh[0] = r;
    }
    __syncthreads();
    float res = sh[0];
    __syncthreads();
    return res;
}

__global__ void ln_kernel(const float* __restrict__ x, const float* __restrict__ w,
                          const float* __restrict__ b, float* __restrict__ out,
                          __half* __restrict__ oh) {
    int row = blockIdx.x, tid = threadIdx.x;
    float4 v = ((const float4*)(x + (size_t)row * CD))[tid];
    float s = blockReduceSum(v.x + v.y + v.z + v.w);
    float mean = s * (1.0f / CD);
    float dx = v.x - mean, dy = v.y - mean, dz = v.z - mean, dw = v.w - mean;
    float s2 = blockReduceSum(dx * dx + dy * dy + dz * dz + dw * dw);
    float rstd = 1.0f / sqrtf(s2 * (1.0f / CD) + 1e-5f);
    float4 wv = ((const float4*)w)[tid], bv = ((const float4*)b)[tid];
    float4 o = make_float4(dx * rstd * wv.x + bv.x, dy * rstd * wv.y + bv.y,
                           dz * rstd * wv.z + bv.z, dw * rstd * wv.w + bv.w);
    ((float4*)(out + (size_t)row * CD))[tid] = o;
    ((uint2*)(oh + (size_t)row * CD))[tid] =
        make_uint2(packh(__float2half_rn(o.x), __float2half_rn(o.y)),
                   packh(__float2half_rn(o.z), __float2half_rn(o.w)));
}

__global__ void ln2_route_kernel(const float* __restrict__ x2, const float* __restrict__ w,
                                 const float* __restrict__ b, const float* __restrict__ conf_rwkv,
                                 const float* __restrict__ conf_trans, const float* __restrict__ w_diff,
                                 const float* __restrict__ W_aff, const float* __restrict__ capital,
                                 __half* __restrict__ hh,
                                 float* __restrict__ conf3, int* __restrict__ winner,
                                 int* __restrict__ rc_cnt, int* __restrict__ rc_list) {
    int row = blockIdx.x, tid = threadIdx.x;
    float4 v = ((const float4*)(x2 + (size_t)row * CD))[tid];
    float s = blockReduceSum(v.x + v.y + v.z + v.w);
    float mean = s * (1.0f / CD);
    float dx = v.x - mean, dy = v.y - mean, dz = v.z - mean, dw = v.w - mean;
    float s2 = blockReduceSum(dx * dx + dy * dy + dz * dz + dw * dw);
    float rstd = 1.0f / sqrtf(s2 * (1.0f / CD) + 1e-5f);
    float4 wv = ((const float4*)w)[tid], bv = ((const float4*)b)[tid];
    float4 o = make_float4(dx * rstd * wv.x + bv.x, dy * rstd * wv.y + bv.y,
                           dz * rstd * wv.z + bv.z, dw * rstd * wv.w + bv.w);
    ((uint2*)(hh + (size_t)row * CD))[tid] =
        make_uint2(packh(__float2half_rn(o.x), __float2half_rn(o.y)),
                   packh(__float2half_rn(o.z), __float2half_rn(o.w)));

    float p[7];
    float4 c0 = ((const float4*)conf_rwkv)[tid];
    float4 c1 = ((const float4*)(conf_rwkv + CD))[tid];
    float4 ct = ((const float4*)conf_trans)[tid];
    float4 wd = ((const float4*)w_diff)[tid];
    p[0] = o.x * c0.x + o.y * c0.y + o.z * c0.z + o.w * c0.w;
    p[1] = o.x * c1.x + o.y * c1.y + o.z * c1.z + o.w * c1.w;
    p[2] = o.x * ct.x + o.y * ct.y + o.z * ct.z + o.w * ct.w;
    p[3] = o.x * wd.x + o.y * wd.y + o.z * wd.z + o.w * wd.w;
    const float* wa = W_aff + (size_t)tid * 12;
#pragma unroll
    for (int e = 0; e < 3; e++)
        p[4 + e] = o.x * wa[e] + o.y * wa[3 + e] + o.z * wa[6 + e] + o.w * wa[9 + e];

    __shared__ float red[7][8];
    int wid = tid >> 5, lid = tid & 31;
#pragma unroll
    for (int q = 0; q < 7; q++) {
        float vv = p[q];
#pragma unroll
        for (int o2 = 16; o2 > 0; o2 >>= 1) vv += __shfl_down_sync(0xffffffffu, vv, o2);
        if (lid == 0) red[q][wid] = vv;
    }
    __syncthreads();
    if (tid == 0) {
        float d[7];
#pragma unroll
        for (int q = 0; q < 7; q++) {
            float t = 0.f;
#pragma unroll
            for (int k = 0; k < 8; k++) t += red[q][k];
            d[q] = t;
        }
        float cf[3] = {sigf(d[0]), sigf(d[1]), sigf(d[2])};
        float diff = sigf(d[3]);
        float bids[3];
#pragma unroll
        for (int e = 0; e < 3; e++) {
            bids[e] = cf[e] * capital[e] * diff + d[4 + e];
            conf3[row * 3 + e] = cf[e];
        }
        int wdx = 0; float best = bids[0];
        if (bids[1] > best) { best = bids[1]; wdx = 1; }
        if (bids[2] > best) { best = bids[2]; wdx = 2; }
        float second = -1e30f;
#pragma unroll
        for (int e = 0; e < 3; e++)
            if (e != wdx && bids[e] > second) second = bids[e];
        winner[row] = wdx;
        if (best - second < 1e-3f) {
            int pos = atomicAdd(rc_cnt, 1);
            if (pos < RC_CAP) rc_list[pos] = row;
        }
    }
}

// exact fp32 recompute of routing for marginal tokens (coalesced row-major GEMV)
__global__ void recheck_kernel(const float* __restrict__ x, const float* __restrict__ xln,
                               const float* __restrict__ Wr, const float* __restrict__ Wv,
                               const float* __restrict__ Wo,
                               const float* __restrict__ ln2w, const float* __restrict__ ln2b,
                               const float* __restrict__ conf_rwkv, const float* __restrict__ conf_trans,
                               const float* __restrict__ w_diff, const float* __restrict__ W_aff,
                               const float* __restrict__ capital,
                               const int* __restrict__ rc_cnt, const int* __restrict__ rc_list,
                               int* __restrict__ winner) {
    int n = *rc_cnt; if (n > RC_CAP) n = RC_CAP;
    int bi = blockIdx.x;
    if (bi >= n) return;
    int row = rc_list[bi];
    int tid = threadIdx.x;
    __shared__ float sx[CD];
    __shared__ float su[CD];
    for (int c = tid; c < CD; c += 256) sx[c] = xln[(size_t)row * CD + c];
    __syncthreads();

    float racc[4] = {0, 0, 0, 0}, vacc[4] = {0, 0, 0, 0};
    for (int k = 0; k < CD; k++) {
        float xv = sx[k];
        const float* wr = Wr + (size_t)k * CD + tid;
        const float* wv = Wv + (size_t)k * CD + tid;
#pragma unroll
        for (int j = 0; j < 4; j++) {
            racc[j] += xv * wr[j * 256];
            vacc[j] += xv * wv[j * 256];
        }
    }
#pragma unroll
    for (int j = 0; j < 4; j++)
        su[tid + j * 256] = sigf(racc[j]) * vacc[j];
    __syncthreads();

    float oacc[4] = {0, 0, 0, 0};
    for (int k = 0; k < CD; k++) {
        float uv = su[k];
        const float* wo = Wo + (size_t)k * CD + tid;
#pragma unroll
        for (int j = 0; j < 4; j++) oacc[j] += uv * wo[j * 256];
    }
    __syncthreads();
#pragma unroll
    for (int j = 0; j < 4; j++)
        sx[tid + j * 256] = oacc[j] + x[(size_t)row * CD + tid + j * 256];
    __syncthreads();

    float ps = 0.f;
    for (int c = tid; c < CD; c += 256) ps += sx[c];
    float mean = blockReduceSum(ps) * (1.0f / CD);
    float ps2 = 0.f;
    for (int c = tid; c < CD; c += 256) { float d = sx[c] - mean; ps2 += d * d; }
    float rstd = 1.0f / sqrtf(blockReduceSum(ps2) * (1.0f / CD) + 1e-5f);

    float p[7] = {0, 0, 0, 0, 0, 0, 0};
    for (int c = tid; c < CD; c += 256) {
        float hc = (sx[c] - mean) * rstd * ln2w[c] + ln2b[c];
        p[0] += hc * conf_rwkv[c];
        p[1] += hc * conf_rwkv[CD + c];
        p[2] += hc * conf_trans[c];
        p[3] += hc * w_diff[c];
        p[4] += hc * W_aff[c * 3 + 0];
        p[5] += hc * W_aff[c * 3 + 1];
        p[6] += hc * W_aff[c * 3 + 2];
    }
    __shared__ float red[7][8];
    int wid = tid >> 5, lid = tid & 31;
#pragma unroll
    for (int q = 0; q < 7; q++) {
        float vv = p[q];
#pragma unroll
        for (int o2 = 16; o2 > 0; o2 >>= 1) vv += __shfl_down_sync(0xffffffffu, vv, o2);
        if (lid == 0) red[q][wid] = vv;
    }
    __syncthreads();
    if (tid == 0) {
        float d[7];
#pragma unroll
        for (int q = 0; q < 7; q++) {
            float t = 0.f;
#pragma unroll
            for (int k = 0; k < 8; k++) t += red[q][k];
            d[q] = t;
        }
        float cf[3] = {sigf(d[0]), sigf(d[1]), sigf(d[2])};
        float diff = sigf(d[3]);
        int wdx = 0; float best = -1e30f;
#pragma unroll
        for (int e = 0; e < 3; e++) {
            float bid = cf[e] * capital[e] * diff + d[4 + e];
            if (bid > best) { best = bid; wdx = e; }
        }
        winner[row] = wdx;
    }
}

__global__ void build_lists(const int* __restrict__ winner, const float* __restrict__ conf3,
                            float* __restrict__ scale_out, int* __restrict__ cnt, int* __restrict__ lst) {
    int i = blockIdx.x * 256 + threadIdx.x;
    if (i >= NT) return;
    int w = winner[i];
    float wc = conf3[i * 3 + w];
    scale_out[i] = wc / (wc + 1e-6f);
    int pos = atomicAdd(&cnt[w], 1);
    lst[w * NT + pos] = i;
}

__global__ void zero_cnt_kernel(int* c, int* rc) {
    if (threadIdx.x < 3) c[threadIdx.x] = 0;
    if (threadIdx.x == 0) *rc = 0;
}

// ================= launch =====================================================
extern "C" void kernel_launch(void* const* d_in, const int* in_sizes, int n_in,
                              void* d_out, int out_size) {
    const float* x = (const float*)d_in[0];
    const float* capital = (const float*)d_in[2];
    const float* ln1w = (const float*)d_in[3], *ln1b = (const float*)d_in[4];
    const float* ln2w = (const float*)d_in[5], *ln2b = (const float*)d_in[6];
    const float* Wr = (const float*)d_in[7], *Wv = (const float*)d_in[8];
    const float* Wo = (const float*)d_in[9], *Ws = (const float*)d_in[10];
    const float* Kr = (const float*)d_in[11], *Vr = (const float*)d_in[12];
    const float* confr = (const float*)d_in[13];
    const float* W1 = (const float*)d_in[14], *W2 = (const float*)d_in[15];
    const float* W3 = (const float*)d_in[16];
    const float* conft = (const float*)d_in[17], *wdiff = (const float*)d_in[18];
    const float* Waff = (const float*)d_in[19];
    float* out = (float*)d_out;

    void* p;
    cudaGetSymbolAddress(&p, g_xln);    float* xln = (float*)p;
    cudaGetSymbolAddress(&p, g_a);      float* ab = (float*)p;
    cudaGetSymbolAddress(&p, g_scale);  float* sclp = (float*)p;
    cudaGetSymbolAddress(&p, g_cnt);    int* cnt = (int*)p;
    cudaGetSymbolAddress(&p, g_list);   int* lst = (int*)p;
    cudaGetSymbolAddress(&p, g_winner); int* win = (int*)p;
    cudaGetSymbolAddress(&p, g_conf3);  float* conf3 = (float*)p;
    cudaGetSymbolAddress(&p, g_rc_cnt); int* rc_cnt = (int*)p;
    cudaGetSymbolAddress(&p, g_rc_list);int* rc_list = (int*)p;
    cudaGetSymbolAddress(&p, g_xh);     __half* xh = (__half*)p;
    cudaGetSymbolAddress(&p, g_hh);     __half* hh = (__half*)p;
    cudaGetSymbolAddress(&p, g_sh);     __half* sh = (__half*)p;
    cudaGetSymbolAddress(&p, g_ah);     __half* ah = (__half*)p;
    cudaGetSymbolAddress(&p, g_hr0);    __half* hr0 = (__half*)p;
    cudaGetSymbolAddress(&p, g_hr1);    __half* hr1 = (__half*)p;
    cudaGetSymbolAddress(&p, g_wt);     __half* wt = (__half*)p;

    cudaFuncSetAttribute(tgemm<TEPI_STORE>,   cudaFuncAttributeMaxDynamicSharedMemorySize, TG_SMEM);
    cudaFuncSetAttribute(tgemm<TEPI_ADDX>,    cudaFuncAttributeMaxDynamicSharedMemorySize, TG_SMEM);
    cudaFuncSetAttribute(tgemm<TEPI_SCATTER>, cudaFuncAttributeMaxDynamicSharedMemorySize, TG_SMEM);
    cudaFuncSetAttribute(tgemm_rv,            cudaFuncAttributeMaxDynamicSharedMemorySize, TG_SMEM);
    cudaFuncSetAttribute((const void*)btgemm<TEPI_CVT, TEPI_STORE, TEPI_HR, TEPI_HR>,
                         cudaFuncAttributeMaxDynamicSharedMemorySize, TG_SMEM);
    cudaFuncSetAttribute((const void*)btgemm<TEPI_GATE, TEPI_SCATTER, TEPI_SCATTER, TEPI_SCATTER>,
                         cudaFuncAttributeMaxDynamicSharedMemorySize, TG_SMEM);

    const size_t M1 = 1048576;
    const size_t KR0T = 0, KR1T = 4 * M1, VR0T = 8 * M1, VR1T = 12 * M1;
    const size_t W1T = 16 * M1, W2T = 17 * M1, W3T = 18 * M1;
    const size_t WRT = 19 * M1, WVT = 20 * M1, WOT = 21 * M1, WST = 22 * M1;

    dim3 blk(256), tb(32, 8);
    dim3 gC(NT / 128, CD / 128);

    // weight transpose+convert (fp16), batched: 3 launches
    {
        TSArgs a{};
        a.W[0] = W1; a.O[0] = wt + W1T;
        a.W[1] = W2; a.O[1] = wt + W2T;
        a.W[2] = W3; a.O[2] = wt + W3T;
        a.W[3] = Wr; a.O[3] = wt + WRT;
        a.W[4] = Wv; a.O[4] = wt + WVT;
        a.W[5] = Wo; a.O[5] = wt + WOT;
        a.W[6] = Ws; a.O[6] = wt + WST;
        a.K = CD; a.N = CD;
        tsplit_b<<<dim3(CD / 32, CD / 32, 7), tb>>>(a);
    }
    {
        TSArgs a{};
        a.W[0] = Kr;                     a.O[0] = wt + KR0T;
        a.W[1] = Kr + (size_t)CD * HD;   a.O[1] = wt + KR1T;
        a.K = CD; a.N = HD;
        tsplit_b<<<dim3(HD / 32, CD / 32, 2), tb>>>(a);
    }
    {
        TSArgs a{};
        a.W[0] = Vr;                     a.O[0] = wt + VR0T;
        a.W[1] = Vr + (size_t)HD * CD;   a.O[1] = wt + VR1T;
        a.K = HD; a.N = CD;
        tsplit_b<<<dim3(CD / 32, HD / 32, 2), tb>>>(a);
    }

    zero_cnt_kernel<<<1, 32>>>(cnt, rc_cnt);
    ln_kernel<<<NT, 256>>>(x, ln1w, ln1b, xln, xh);

    // attention path: fused sigmoid(x@Wr)*(x@Wv) -> ah, then @Wo + x -> out
    tgemm_rv<<<dim3(NT / 128, CD / 64), blk, TG_SMEM>>>(xh, wt + WRT, wt + WVT, CD, ah, CD);
    tgemm<TEPI_ADDX><<<gC, blk, TG_SMEM>>>(ah, wt + WOT, NT, nullptr, CD,
                                           nullptr, x, nullptr, nullptr, out, nullptr, CD);

    // routing (provisional, flags marginal tokens) -> exact recheck -> lists
    ln2_route_kernel<<<NT, 256>>>(out, ln2w, ln2b, confr, conft, wdiff, Waff, capital,
                                  hh, conf3, win, rc_cnt, rc_list);
    recheck_kernel<<<RC_CAP, 256>>>(x, xln, Wr, Wv, Wo, ln2w, ln2b, confr, conft, wdiff,
                                    Waff, capital, rc_cnt, rc_list, win);
    build_lists<<<NT / 256, 256>>>(win, conf3, sclp, cnt, lst);

    // ---- batched expert set 1: {Ws(sparse,cvt), W1, K0, K1} ----
    GDesc dws = {xh, wt + WST, cnt + 2, lst + 2 * NT,
                 nullptr, nullptr, nullptr, nullptr, sh, CD, CD, 8};
    GDesc dw1 = {hh, wt + W1T, cnt + 2, lst + 2 * NT,
                 nullptr, nullptr, nullptr, ab, nullptr, CD, CD, 8};
    GDesc dk0 = {hh, wt + KR0T, cnt + 0, lst + 0 * NT,
                 nullptr, nullptr, nullptr, nullptr, hr0, CD, HD, 32};
    GDesc dk1 = {hh, wt + KR1T, cnt + 1, lst + 1 * NT,
                 nullptr, nullptr, nullptr, nullptr, hr1, CD, HD, 32};
    btgemm<TEPI_CVT, TEPI_STORE, TEPI_HR, TEPI_HR>
        <<<dim3(NT / 128, 32, 4), blk, TG_SMEM>>>(dws, dw1, dk0, dk1);

    // ---- batched expert set 2: {W2(gate), V0, V1} ----
    GDesc dw2 = {sh, wt + W2T, cnt + 2, nullptr,
                 ab, nullptr, nullptr, nullptr, ah, CD, CD, 8};
    GDesc dv0 = {hr0, wt + VR0T, cnt + 0, nullptr,
                 nullptr, lst + 0 * NT, sclp, out, nullptr, HD, CD, 8};
    GDesc dv1 = {hr1, wt + VR1T, cnt + 1, nullptr,
                 nullptr, lst + 1 * NT, sclp, out, nullptr, HD, CD, 8};
    btgemm<TEPI_GATE, TEPI_SCATTER, TEPI_SCATTER, TEPI_SCATTER>
        <<<dim3(NT / 128, 8, 3), blk, TG_SMEM>>>(dw2, dv0, dv1, dv1);

    // ---- set 3: W3 (scatter) ----
    tgemm<TEPI_SCATTER><<<gC, blk, TG_SMEM>>>(ah, wt + W3T, 0, cnt + 2, CD,
                                              nullptr, nullptr, lst + 2 * NT, sclp, out, nullptr, CD);
}